// round 8
// baseline (speedup 1.0000x reference)
#include <cuda_runtime.h>
#include <math.h>

// ---------------- problem constants ----------------
#define HIDC 128
#define NMAX 50000
#define EMAX 600000

// ---------------- device scratch (allowed: __device__ globals) ----------------
__device__ __align__(128) float g_h    [NMAX * HIDC];   // layer input / residual
__device__ __align__(128) float g_xh   [NMAX * HIDC];   // h @ W_lin
__device__ __align__(128) float g_acc  [NMAX * HIDC];   // attention accumulator -> pre-BN g
__device__ __align__(128) float g_alpha[EMAX * 4];      // per-edge attention logits
__device__ __align__(128) float g_asrc [NMAX * 4];
__device__ __align__(128) float g_adst [NMAX * 4];
__device__ __align__(128) float g_aself[NMAX * 4];
__device__ __align__(128) float g_amax [NMAX * 4];
__device__ __align__(128) float g_den  [NMAX * 4];
__device__ __align__(128) float g_deg  [NMAX];
__device__ __align__(128) float g_easum[NMAX * 16];
__device__ __align__(128) float g_M    [3 * 64];        // W_bond @ Ve  [16][4] per layer
__device__ __align__(128) float g_c    [3 * 4];         // b_bond . Ve  per layer
__device__ double g_bnsum[HIDC];
__device__ double g_bnsq [HIDC];
__device__ __align__(128) float g_bnscale[HIDC];
__device__ __align__(128) float g_bnshift[HIDC];

// ---------------- helpers ----------------
__device__ __forceinline__ void redAdd4(float* addr, float4 v) {
    asm volatile("red.global.add.v4.f32 [%0], {%1, %2, %3, %4};"
                 :: "l"(addr), "f"(v.x), "f"(v.y), "f"(v.z), "f"(v.w) : "memory");
}

__device__ __forceinline__ void atomicMaxF(float* addr, float v) {
    if (v >= 0.f) atomicMax((int*)addr, __float_as_int(v));
    else          atomicMin((unsigned int*)addr, __float_as_uint(v));
}

__device__ __forceinline__ float lrelu(float a) { return a > 0.f ? a : 0.2f * a; }

// ---------------- zero deg / easum ----------------
__global__ void prep_zero_kernel(int N) {
    int i = blockIdx.x * blockDim.x + threadIdx.x;
    if (i < N)      g_deg[i]   = 0.f;
    if (i < N * 16) g_easum[i] = 0.f;
}

// ---------------- per-layer folded constants: M = W_bond @ Ve, c = b_bond . Ve ----------------
__global__ void consts_kernel(const float* __restrict__ W_edge,
                              const float* __restrict__ att_edge,
                              const float* __restrict__ W_bond,
                              const float* __restrict__ b_bond) {
    __shared__ float Ve[128 * 4];
    int t = threadIdx.x; // 128 threads
    for (int l = 0; l < 3; l++) {
        const float* We = W_edge + l * 128 * 128 + t * 128;
        const float* ae = att_edge + l * 128;
        float v0 = 0.f, v1 = 0.f, v2 = 0.f, v3 = 0.f;
        for (int d = 0; d < 32; d++) {
            v0 += We[d]      * ae[d];
            v1 += We[32 + d] * ae[32 + d];
            v2 += We[64 + d] * ae[64 + d];
            v3 += We[96 + d] * ae[96 + d];
        }
        Ve[t * 4 + 0] = v0; Ve[t * 4 + 1] = v1; Ve[t * 4 + 2] = v2; Ve[t * 4 + 3] = v3;
        __syncthreads();
        if (t < 16) {
            float m0 = 0.f, m1 = 0.f, m2 = 0.f, m3 = 0.f;
            for (int k = 0; k < 128; k++) {
                float w = W_bond[t * 128 + k];
                m0 += w * Ve[k * 4 + 0]; m1 += w * Ve[k * 4 + 1];
                m2 += w * Ve[k * 4 + 2]; m3 += w * Ve[k * 4 + 3];
            }
            g_M[l * 64 + t * 4 + 0] = m0; g_M[l * 64 + t * 4 + 1] = m1;
            g_M[l * 64 + t * 4 + 2] = m2; g_M[l * 64 + t * 4 + 3] = m3;
        } else if (t < 20) {
            int h = t - 16;
            float cc = 0.f;
            for (int k = 0; k < 128; k++) cc += b_bond[k] * Ve[k * 4 + h];
            g_c[l * 4 + h] = cc;
        }
        __syncthreads();
    }
}

// ---------------- degree + segment_sum(edge_attr) over dst ----------------
__global__ void edge_prep_kernel(const int* __restrict__ ei,
                                 const float* __restrict__ edge_attr, int E) {
    int e = blockIdx.x * blockDim.x + threadIdx.x;
    if (e >= E) return;
    int d = ei[E + e];
    atomicAdd(&g_deg[d], 1.f);
    const float4* ev = ((const float4*)edge_attr) + e * 4;
#pragma unroll
    for (int q = 0; q < 4; q++) redAdd4(&g_easum[d * 16 + 4 * q], ev[q]);
}

// ---------------- GEMM: C[M,128] = A[M,K] @ B[K,128] (+ bias) ----------------
template <int K>
__global__ __launch_bounds__(256) void gemm_kernel(const float* __restrict__ A,
                                                   const float* __restrict__ B,
                                                   const float* __restrict__ bias,
                                                   float* __restrict__ C, int M) {
    extern __shared__ float sm[];
    float* Bs = sm;               // K*128
    float* As = sm + K * 128;     // 64*(K+1), row-major padded
    const int t = threadIdx.x;
    const int row0 = blockIdx.x * 64;

    for (int idx = t; idx < K * 32; idx += 256)
        ((float4*)Bs)[idx] = ((const float4*)B)[idx];

    constexpr int KQ = K / 4;
    for (int idx = t; idx < 64 * KQ; idx += 256) {
        int r = idx / KQ, q = idx - r * KQ;
        int grow = row0 + r;
        float4 v = make_float4(0.f, 0.f, 0.f, 0.f);
        if (grow < M) v = ((const float4*)(A + (size_t)grow * K))[q];
        float* dp = As + r * (K + 1) + 4 * q;
        dp[0] = v.x; dp[1] = v.y; dp[2] = v.z; dp[3] = v.w;
    }
    __syncthreads();

    const int j = t & 15;   // col group: cols 8j..8j+7
    const int i = t >> 4;   // row group: rows 4i..4i+3
    float acc[4][8];
#pragma unroll
    for (int r = 0; r < 4; r++)
#pragma unroll
        for (int cc = 0; cc < 8; cc++) acc[r][cc] = 0.f;

    const float* a0 = As + (4 * i) * (K + 1);
    const float4* Bs4 = (const float4*)Bs;
#pragma unroll 8
    for (int k = 0; k < K; k++) {
        float av[4];
        av[0] = a0[k];
        av[1] = a0[k + (K + 1)];
        av[2] = a0[k + 2 * (K + 1)];
        av[3] = a0[k + 3 * (K + 1)];
        float4 b0 = Bs4[k * 32 + 2 * j];
        float4 b1 = Bs4[k * 32 + 2 * j + 1];
#pragma unroll
        for (int r = 0; r < 4; r++) {
            acc[r][0] += av[r] * b0.x; acc[r][1] += av[r] * b0.y;
            acc[r][2] += av[r] * b0.z; acc[r][3] += av[r] * b0.w;
            acc[r][4] += av[r] * b1.x; acc[r][5] += av[r] * b1.y;
            acc[r][6] += av[r] * b1.z; acc[r][7] += av[r] * b1.w;
        }
    }

    float4 bb0 = make_float4(0.f, 0.f, 0.f, 0.f), bb1 = bb0;
    if (bias) { bb0 = ((const float4*)bias)[2 * j]; bb1 = ((const float4*)bias)[2 * j + 1]; }
#pragma unroll
    for (int r = 0; r < 4; r++) {
        int grow = row0 + 4 * i + r;
        if (grow >= M) continue;
        float4 o0 = make_float4(acc[r][0] + bb0.x, acc[r][1] + bb0.y,
                                acc[r][2] + bb0.z, acc[r][3] + bb0.w);
        float4 o1 = make_float4(acc[r][4] + bb1.x, acc[r][5] + bb1.y,
                                acc[r][6] + bb1.z, acc[r][7] + bb1.w);
        float4* cp = (float4*)(C + (size_t)grow * 128);
        cp[2 * j] = o0;
        cp[2 * j + 1] = o1;
    }
}

// ---------------- node pass 1: a_src/a_dst, self-loop logit, init amax/den/acc ----------------
__global__ void node1_kernel(const float* __restrict__ att_src,
                             const float* __restrict__ att_dst,
                             int l, int N) {
    if (blockIdx.x == 0 && threadIdx.x < 128) {
        g_bnsum[threadIdx.x] = 0.0;
        g_bnsq[threadIdx.x] = 0.0;
    }
    int gt = blockIdx.x * blockDim.x + threadIdx.x;
    int nRaw = gt >> 5;
    bool valid = nRaw < N;
    int n = valid ? nRaw : (N - 1);
    int lane = gt & 31;

    float4 xv = ((const float4*)g_xh)[n * 32 + lane];
    float4 sv = ((const float4*)(att_src + l * 128))[lane];
    float4 dv = ((const float4*)(att_dst + l * 128))[lane];
    float ps = xv.x * sv.x + xv.y * sv.y + xv.z * sv.z + xv.w * sv.w;
    float pd = xv.x * dv.x + xv.y * dv.y + xv.z * dv.z + xv.w * dv.w;
#pragma unroll
    for (int off = 4; off > 0; off >>= 1) {
        ps += __shfl_xor_sync(0xffffffffu, ps, off);
        pd += __shfl_xor_sync(0xffffffffu, pd, off);
    }
    if (!valid) return;
    ((float4*)g_acc)[n * 32 + lane] = make_float4(0.f, 0.f, 0.f, 0.f);
    if ((lane & 7) == 0) {
        int h = lane >> 3;
        float ael = 0.f;
        float degv = g_deg[n];
        if (degv > 0.f) {
            const float* es = g_easum + n * 16;
            const float* Mh = g_M + l * 64 + h;
            float sacc = 0.f;
#pragma unroll
            for (int k = 0; k < 16; k++) sacc += es[k] * Mh[k * 4];
            ael = sacc / degv + g_c[l * 4 + h];
        }
        float a = lrelu(ps + pd + ael);
        g_asrc[n * 4 + h] = ps;
        g_adst[n * 4 + h] = pd;
        g_aself[n * 4 + h] = a;
        g_amax[n * 4 + h] = a;   // self-loop seeds the segment max
        g_den[n * 4 + h] = 0.f;
    }
}

// ---------------- edge pass 1: logits + segment max ----------------
__global__ void edge_max_kernel(const int* __restrict__ ei,
                                const float* __restrict__ edge_attr,
                                int l, int E) {
    __shared__ float Ms[64];
    __shared__ float Cs[4];
    if (threadIdx.x < 64) Ms[threadIdx.x] = g_M[l * 64 + threadIdx.x];
    if (threadIdx.x < 4)  Cs[threadIdx.x] = g_c[l * 4 + threadIdx.x];
    __syncthreads();
    int e = blockIdx.x * blockDim.x + threadIdx.x;
    if (e >= E) return;
    int s = ei[e], d = ei[E + e];
    float4 as = ((const float4*)g_asrc)[s];
    float4 ad = ((const float4*)g_adst)[d];
    float ev[16];
    const float4* ep = ((const float4*)edge_attr) + e * 4;
#pragma unroll
    for (int q = 0; q < 4; q++) {
        float4 v = ep[q];
        ev[4 * q] = v.x; ev[4 * q + 1] = v.y; ev[4 * q + 2] = v.z; ev[4 * q + 3] = v.w;
    }
    float ae0 = Cs[0], ae1 = Cs[1], ae2 = Cs[2], ae3 = Cs[3];
#pragma unroll
    for (int k = 0; k < 16; k++) {
        float v = ev[k];
        ae0 += v * Ms[k * 4 + 0]; ae1 += v * Ms[k * 4 + 1];
        ae2 += v * Ms[k * 4 + 2]; ae3 += v * Ms[k * 4 + 3];
    }
    float a0 = lrelu(as.x + ad.x + ae0);
    float a1 = lrelu(as.y + ad.y + ae1);
    float a2 = lrelu(as.z + ad.z + ae2);
    float a3 = lrelu(as.w + ad.w + ae3);
    ((float4*)g_alpha)[e] = make_float4(a0, a1, a2, a3);
    atomicMaxF(&g_amax[4 * d + 0], a0);
    atomicMaxF(&g_amax[4 * d + 1], a1);
    atomicMaxF(&g_amax[4 * d + 2], a2);
    atomicMaxF(&g_amax[4 * d + 3], a3);
}

// ---------------- edge pass 2: exp + den + weighted scatter (8 threads / edge) ----------------
__global__ void edge_acc_kernel(const int* __restrict__ ei, int E) {
    int gt = blockIdx.x * blockDim.x + threadIdx.x;
    int eRaw = gt >> 3;
    bool valid = eRaw < E;
    int e = valid ? eRaw : (E - 1);
    int u = gt & 7;
    int s = __ldg(ei + e), d = __ldg(ei + E + e);

    float ex = 0.f;
    if (u < 4) {
        float a = g_alpha[4 * e + u];
        float m = g_amax[4 * d + u];
        ex = __expf(a - m);
        if (valid) atomicAdd(&g_den[4 * d + u], ex);
    }
    int gb = (threadIdx.x & 31) & ~7;
    float w0 = __shfl_sync(0xffffffffu, ex, gb + 0);
    float w1 = __shfl_sync(0xffffffffu, ex, gb + 1);
    float w2 = __shfl_sync(0xffffffffu, ex, gb + 2);
    float w3 = __shfl_sync(0xffffffffu, ex, gb + 3);
    if (!valid) return;

    float wq[4] = { w0, w1, w2, w3 };
    const float4* xr = (const float4*)(g_xh + (size_t)s * 128);
    float* oc = g_acc + (size_t)d * 128;
#pragma unroll
    for (int q = 0; q < 4; q++) {
        float4 v = xr[u + 8 * q];   // channel block = head q, perfectly coalesced per q
        float w = wq[q];
        v.x *= w; v.y *= w; v.z *= w; v.w *= w;
        redAdd4(oc + 4 * (u + 8 * q), v);
    }
}

// ---------------- node pass 2: self-loop term, normalize, bias, BN partial sums ----------------
__global__ void node2_kernel(const float* __restrict__ bias_conv, int l, int N) {
    __shared__ float ws[2][4];
    __shared__ float rden[2][4];
    int c = threadIdx.x;          // 128 threads = channels
    int h = c >> 5;
    const float bc = bias_conv[l * 128 + c];
    float s1 = 0.f, s2 = 0.f;
    int p = 0;
    for (int n = blockIdx.x; n < N; n += gridDim.x) {
        if (c < 4) {
            float wsf = __expf(g_aself[n * 4 + c] - g_amax[n * 4 + c]);
            ws[p][c] = wsf;
            rden[p][c] = 1.f / (g_den[n * 4 + c] + wsf + 1e-16f);
        }
        __syncthreads();
        float g = (g_acc[n * 128 + c] + ws[p][h] * g_xh[n * 128 + c]) * rden[p][h] + bc;
        g_acc[n * 128 + c] = g;
        s1 += g;
        s2 += g * g;
        p ^= 1;
    }
    atomicAdd(&g_bnsum[c], (double)s1);
    atomicAdd(&g_bnsq[c], (double)s2);
}

// ---------------- BN stats -> scale/shift ----------------
__global__ void bnstats_kernel(const float* __restrict__ gamma,
                               const float* __restrict__ beta, int l, int N) {
    int c = threadIdx.x;
    double mu = g_bnsum[c] / (double)N;
    double var = g_bnsq[c] / (double)N - mu * mu;
    float rstd = (float)rsqrt(var + 1e-5);
    float ga = gamma[l * 128 + c];
    g_bnscale[c] = ga * rstd;
    g_bnshift[c] = beta[l * 128 + c] - ga * (float)mu * rstd;
}

// ---------------- node pass 3: BN + relu + residual -> g_h ----------------
__global__ void node3_kernel(int N) {
    int idx = blockIdx.x * blockDim.x + threadIdx.x;
    if (idx >= N * 32) return;
    int q = idx & 31;
    float4 g = ((const float4*)g_acc)[idx];
    float4 hi = ((const float4*)g_h)[idx];
    float4 sc = ((const float4*)g_bnscale)[q];
    float4 sh = ((const float4*)g_bnshift)[q];
    float4 o;
    o.x = fmaxf(fmaf(g.x, sc.x, sh.x), 0.f) + hi.x;
    o.y = fmaxf(fmaf(g.y, sc.y, sh.y), 0.f) + hi.y;
    o.z = fmaxf(fmaf(g.z, sc.z, sh.z), 0.f) + hi.z;
    o.w = fmaxf(fmaf(g.w, sc.w, sh.w), 0.f) + hi.w;
    ((float4*)g_h)[idx] = o;
}

// ---------------- launcher ----------------
extern "C" void kernel_launch(void* const* d_in, const int* in_sizes, int n_in,
                              void* d_out, int out_size) {
    (void)n_in; (void)out_size;
    const float* x         = (const float*)d_in[0];
    const int*   ei        = (const int*)  d_in[1];
    const float* edge_attr = (const float*)d_in[2];
    const float* W_atom    = (const float*)d_in[3];
    const float* b_atom    = (const float*)d_in[4];
    const float* W_bond    = (const float*)d_in[5];
    const float* b_bond    = (const float*)d_in[6];
    const float* W_lin     = (const float*)d_in[7];
    const float* W_edge    = (const float*)d_in[8];
    const float* att_src   = (const float*)d_in[9];
    const float* att_dst   = (const float*)d_in[10];
    const float* att_edge  = (const float*)d_in[11];
    const float* bias_conv = (const float*)d_in[12];
    const float* bn_gamma  = (const float*)d_in[13];
    const float* bn_beta   = (const float*)d_in[14];
    const float* W_out     = (const float*)d_in[15];
    const float* b_out     = (const float*)d_in[16];
    float* out = (float*)d_out;

    const int N = in_sizes[0] / 64;
    const int E = in_sizes[1] / 2;

    const int smem128 = (128 * 128 + 64 * 129) * 4;  // 98560
    const int smem64  = (64 * 128 + 64 * 65) * 4;    // 49408
    cudaFuncSetAttribute(gemm_kernel<128>, cudaFuncAttributeMaxDynamicSharedMemorySize, smem128);
    cudaFuncSetAttribute(gemm_kernel<64>,  cudaFuncAttributeMaxDynamicSharedMemorySize, smem64);

    float* ph;  cudaGetSymbolAddress((void**)&ph,  g_h);
    float* pxh; cudaGetSymbolAddress((void**)&pxh, g_xh);

    // preprocessing (deg, segment_sum(edge_attr), folded layer constants)
    prep_zero_kernel<<<(N * 16 + 255) / 256, 256>>>(N);
    consts_kernel<<<1, 128>>>(W_edge, att_edge, W_bond, b_bond);
    edge_prep_kernel<<<(E + 255) / 256, 256>>>(ei, edge_attr, E);

    // atom embedding: h = x @ W_atom + b_atom
    gemm_kernel<64><<<(N + 63) / 64, 256, smem64>>>(x, W_atom, b_atom, ph, N);

    for (int l = 0; l < 3; l++) {
        gemm_kernel<128><<<(N + 63) / 64, 256, smem128>>>(ph, W_lin + l * 128 * 128, nullptr, pxh, N);
        node1_kernel<<<(N * 32 + 255) / 256, 256>>>(att_src, att_dst, l, N);
        edge_max_kernel<<<(E + 255) / 256, 256>>>(ei, edge_attr, l, E);
        edge_acc_kernel<<<(E * 8 + 255) / 256, 256>>>(ei, E);
        node2_kernel<<<512, 128>>>(bias_conv, l, N);
        bnstats_kernel<<<1, 128>>>(bn_gamma, bn_beta, l, N);
        node3_kernel<<<(N * 32 + 255) / 256, 256>>>(N);
    }

    // output projection
    gemm_kernel<128><<<(N + 63) / 64, 256, smem128>>>(ph, W_out, b_out, out, N);
}

// round 9
// speedup vs baseline: 1.2787x; 1.2787x over previous
#include <cuda_runtime.h>
#include <math.h>

// ---------------- problem constants ----------------
#define HIDC 128
#define NMAX 50000
#define EMAX 600000
#define SCAN_BLK 512

// ---------------- device scratch ----------------
__device__ __align__(128) float g_h    [NMAX * HIDC];
__device__ __align__(128) float g_xh   [NMAX * HIDC];
__device__ __align__(128) float g_acc  [NMAX * HIDC];
__device__ __align__(128) float g_asrc [NMAX * 4];
__device__ __align__(128) float g_adst [NMAX * 4];
__device__ __align__(128) float g_aself[NMAX * 4];
__device__ __align__(128) float g_wself[NMAX * 4];
__device__ __align__(128) float g_rden [NMAX * 4];
__device__ __align__(128) float g_easum[NMAX * 16];
__device__ __align__(128) float g_M    [3 * 64];
__device__ __align__(128) float g_c    [3 * 4];
__device__ int   g_degi  [NMAX];
__device__ int   g_fill  [NMAX];
__device__ int   g_rowptr[NMAX];
__device__ int   g_bsum  [256];
__device__ __align__(128) int   g_csrc[EMAX];
__device__ __align__(128) float g_ae  [3][EMAX * 4];   // folded edge logits, CSR order
__device__ __align__(128) float g_w   [EMAX * 4];      // per-edge softmax weights (unnorm exp)
__device__ double g_bnsum[HIDC];
__device__ double g_bnsq [HIDC];
__device__ __align__(128) float g_bnscale[HIDC];
__device__ __align__(128) float g_bnshift[HIDC];

// ---------------- helpers ----------------
__device__ __forceinline__ void redAdd4(float* addr, float4 v) {
    asm volatile("red.global.add.v4.f32 [%0], {%1, %2, %3, %4};"
                 :: "l"(addr), "f"(v.x), "f"(v.y), "f"(v.z), "f"(v.w) : "memory");
}
__device__ __forceinline__ float lrelu(float a) { return a > 0.f ? a : 0.2f * a; }

// ---------------- prep: zeros ----------------
__global__ void prep_zero_kernel(int N) {
    int i = blockIdx.x * blockDim.x + threadIdx.x;
    if (i < N)      { g_degi[i] = 0; g_fill[i] = 0; }
    if (i < N * 16) g_easum[i] = 0.f;
}

// ---------------- per-layer folded constants: M = W_bond @ Ve, c = b_bond . Ve ----------------
__global__ void consts_kernel(const float* __restrict__ W_edge,
                              const float* __restrict__ att_edge,
                              const float* __restrict__ W_bond,
                              const float* __restrict__ b_bond) {
    __shared__ float Ve[128 * 4];
    int t = threadIdx.x; // 128 threads
    for (int l = 0; l < 3; l++) {
        const float* We = W_edge + l * 128 * 128 + t * 128;
        const float* ae = att_edge + l * 128;
        float v0 = 0.f, v1 = 0.f, v2 = 0.f, v3 = 0.f;
        for (int d = 0; d < 32; d++) {
            v0 += We[d]      * ae[d];
            v1 += We[32 + d] * ae[32 + d];
            v2 += We[64 + d] * ae[64 + d];
            v3 += We[96 + d] * ae[96 + d];
        }
        Ve[t * 4 + 0] = v0; Ve[t * 4 + 1] = v1; Ve[t * 4 + 2] = v2; Ve[t * 4 + 3] = v3;
        __syncthreads();
        if (t < 16) {
            float m0 = 0.f, m1 = 0.f, m2 = 0.f, m3 = 0.f;
            for (int k = 0; k < 128; k++) {
                float w = W_bond[t * 128 + k];
                m0 += w * Ve[k * 4 + 0]; m1 += w * Ve[k * 4 + 1];
                m2 += w * Ve[k * 4 + 2]; m3 += w * Ve[k * 4 + 3];
            }
            g_M[l * 64 + t * 4 + 0] = m0; g_M[l * 64 + t * 4 + 1] = m1;
            g_M[l * 64 + t * 4 + 2] = m2; g_M[l * 64 + t * 4 + 3] = m3;
        } else if (t < 20) {
            int h = t - 16;
            float cc = 0.f;
            for (int k = 0; k < 128; k++) cc += b_bond[k] * Ve[k * 4 + h];
            g_c[l * 4 + h] = cc;
        }
        __syncthreads();
    }
}

// ---------------- degree + segment_sum(edge_attr) over dst ----------------
__global__ void edge_prep_kernel(const int* __restrict__ ei,
                                 const float* __restrict__ edge_attr, int E) {
    int e = blockIdx.x * blockDim.x + threadIdx.x;
    if (e >= E) return;
    int d = ei[E + e];
    atomicAdd(&g_degi[d], 1);
    const float4* ev = ((const float4*)edge_attr) + e * 4;
#pragma unroll
    for (int q = 0; q < 4; q++) redAdd4(&g_easum[d * 16 + 4 * q], ev[q]);
}

// ---------------- exclusive scan of degi -> rowptr (3 kernels) ----------------
__global__ void scan_sum_kernel(int N) {
    __shared__ int sh[16];
    int b = blockIdx.x, t = threadIdx.x;
    int i = b * SCAN_BLK + t;
    int v = (i < N) ? g_degi[i] : 0;
#pragma unroll
    for (int o = 16; o; o >>= 1) v += __shfl_xor_sync(0xffffffffu, v, o);
    if ((t & 31) == 0) sh[t >> 5] = v;
    __syncthreads();
    if (t < 16) {
        int s = sh[t];
#pragma unroll
        for (int o = 8; o; o >>= 1) s += __shfl_xor_sync(0xffffu, s, o);
        if (t == 0) g_bsum[b] = s;
    }
}
__global__ void scan_mid_kernel(int nb) {
    if (threadIdx.x == 0) {
        int acc = 0;
        for (int b = 0; b < nb; b++) { int v = g_bsum[b]; g_bsum[b] = acc; acc += v; }
    }
}
__global__ void scan_final_kernel(int N) {
    __shared__ int wsum[16];
    int b = blockIdx.x, t = threadIdx.x;
    int i = b * SCAN_BLK + t;
    int v = (i < N) ? g_degi[i] : 0;
    int x = v;
#pragma unroll
    for (int o = 1; o < 32; o <<= 1) {
        int y = __shfl_up_sync(0xffffffffu, x, o);
        if ((t & 31) >= o) x += y;
    }
    if ((t & 31) == 31) wsum[t >> 5] = x;
    __syncthreads();
    if (t == 0) {
        int acc = 0;
        for (int w = 0; w < 16; w++) { int s = wsum[w]; wsum[w] = acc; acc += s; }
    }
    __syncthreads();
    if (i < N) g_rowptr[i] = x - v + wsum[t >> 5] + g_bsum[b];
}

// ---------------- counting-sort scatter: csr_src + folded edge logits per layer ----------------
__global__ void scatter_kernel(const int* __restrict__ ei,
                               const float* __restrict__ edge_attr, int E) {
    __shared__ float Ms[192];
    __shared__ float Cs[12];
    int t = threadIdx.x;
    if (t < 192) Ms[t] = g_M[t];
    if (t < 12)  Cs[t] = g_c[t];
    __syncthreads();
    int e = blockIdx.x * blockDim.x + t;
    if (e >= E) return;
    int s = ei[e], d = ei[E + e];
    int pos = g_rowptr[d] + atomicAdd(&g_fill[d], 1);
    g_csrc[pos] = s;
    float ev[16];
    const float4* ep = ((const float4*)edge_attr) + e * 4;
#pragma unroll
    for (int q = 0; q < 4; q++) {
        float4 v = ep[q];
        ev[4 * q] = v.x; ev[4 * q + 1] = v.y; ev[4 * q + 2] = v.z; ev[4 * q + 3] = v.w;
    }
#pragma unroll
    for (int l = 0; l < 3; l++) {
        float a0 = Cs[l * 4 + 0], a1 = Cs[l * 4 + 1], a2 = Cs[l * 4 + 2], a3 = Cs[l * 4 + 3];
#pragma unroll
        for (int k = 0; k < 16; k++) {
            float v = ev[k];
            a0 += v * Ms[l * 64 + k * 4 + 0]; a1 += v * Ms[l * 64 + k * 4 + 1];
            a2 += v * Ms[l * 64 + k * 4 + 2]; a3 += v * Ms[l * 64 + k * 4 + 3];
        }
        ((float4*)g_ae[l])[pos] = make_float4(a0, a1, a2, a3);
    }
}

// ---------------- GEMM: C[M,128] = A[M,K] @ B[K,128] (+ bias) ----------------
template <int K>
__global__ __launch_bounds__(256) void gemm_kernel(const float* __restrict__ A,
                                                   const float* __restrict__ B,
                                                   const float* __restrict__ bias,
                                                   float* __restrict__ C, int M) {
    constexpr int AST = K + 4;  // padded row stride (floats), 16B-aligned
    extern __shared__ float sm[];
    float* Bs = sm;               // K*128
    float* As = sm + K * 128;     // 64*AST
    const int t = threadIdx.x;
    const int row0 = blockIdx.x * 64;

    for (int idx = t; idx < K * 32; idx += 256)
        ((float4*)Bs)[idx] = ((const float4*)B)[idx];

    constexpr int KQ = K / 4;
    for (int idx = t; idx < 64 * KQ; idx += 256) {
        int r = idx / KQ, q = idx - r * KQ;
        int grow = row0 + r;
        float4 v = make_float4(0.f, 0.f, 0.f, 0.f);
        if (grow < M) v = ((const float4*)(A + (size_t)grow * K))[q];
        *(float4*)(As + r * AST + 4 * q) = v;
    }
    __syncthreads();

    const int j = t & 15;   // cols 8j..8j+7
    const int i = t >> 4;   // rows 4i..4i+3
    float acc[4][8];
#pragma unroll
    for (int r = 0; r < 4; r++)
#pragma unroll
        for (int cc = 0; cc < 8; cc++) acc[r][cc] = 0.f;

    const float* aBase = As + (4 * i) * AST;
    const float4* Bs4 = (const float4*)Bs;
#pragma unroll 2
    for (int k4 = 0; k4 < K / 4; k4++) {
        float4 av[4];
#pragma unroll
        for (int r = 0; r < 4; r++)
            av[r] = *(const float4*)(aBase + r * AST + 4 * k4);
#pragma unroll
        for (int kk = 0; kk < 4; kk++) {
            int k = 4 * k4 + kk;
            float4 b0 = Bs4[k * 32 + 2 * j];
            float4 b1 = Bs4[k * 32 + 2 * j + 1];
#pragma unroll
            for (int r = 0; r < 4; r++) {
                float a = ((const float*)&av[r])[kk];
                acc[r][0] += a * b0.x; acc[r][1] += a * b0.y;
                acc[r][2] += a * b0.z; acc[r][3] += a * b0.w;
                acc[r][4] += a * b1.x; acc[r][5] += a * b1.y;
                acc[r][6] += a * b1.z; acc[r][7] += a * b1.w;
            }
        }
    }

    float4 bb0 = make_float4(0.f, 0.f, 0.f, 0.f), bb1 = bb0;
    if (bias) { bb0 = ((const float4*)bias)[2 * j]; bb1 = ((const float4*)bias)[2 * j + 1]; }
#pragma unroll
    for (int r = 0; r < 4; r++) {
        int grow = row0 + 4 * i + r;
        if (grow >= M) continue;
        float4* cp = (float4*)(C + (size_t)grow * 128);
        cp[2 * j]     = make_float4(acc[r][0] + bb0.x, acc[r][1] + bb0.y,
                                    acc[r][2] + bb0.z, acc[r][3] + bb0.w);
        cp[2 * j + 1] = make_float4(acc[r][4] + bb1.x, acc[r][5] + bb1.y,
                                    acc[r][6] + bb1.z, acc[r][7] + bb1.w);
    }
}

// ---------------- node pass 1: a_src/a_dst/a_self ----------------
__global__ void node1_kernel(const float* __restrict__ att_src,
                             const float* __restrict__ att_dst,
                             int l, int N) {
    if (blockIdx.x == 0 && threadIdx.x < 128) {
        g_bnsum[threadIdx.x] = 0.0;
        g_bnsq[threadIdx.x] = 0.0;
    }
    int gt = blockIdx.x * blockDim.x + threadIdx.x;
    int nRaw = gt >> 5;
    bool valid = nRaw < N;
    int n = valid ? nRaw : (N - 1);
    int lane = gt & 31;

    float4 xv = ((const float4*)g_xh)[n * 32 + lane];
    float4 sv = ((const float4*)(att_src + l * 128))[lane];
    float4 dv = ((const float4*)(att_dst + l * 128))[lane];
    float ps = xv.x * sv.x + xv.y * sv.y + xv.z * sv.z + xv.w * sv.w;
    float pd = xv.x * dv.x + xv.y * dv.y + xv.z * dv.z + xv.w * dv.w;
#pragma unroll
    for (int off = 4; off > 0; off >>= 1) {
        ps += __shfl_xor_sync(0xffffffffu, ps, off);
        pd += __shfl_xor_sync(0xffffffffu, pd, off);
    }
    if (!valid || (lane & 7)) return;
    int h = lane >> 3;
    float ael = 0.f;
    float degv = (float)g_degi[n];
    if (degv > 0.f) {
        const float* es = g_easum + n * 16;
        const float* Mh = g_M + l * 64 + h;
        float sacc = 0.f;
#pragma unroll
        for (int k = 0; k < 16; k++) sacc += es[k] * Mh[k * 4];
        ael = sacc / degv + g_c[l * 4 + h];
    }
    g_asrc[n * 4 + h] = ps;
    g_adst[n * 4 + h] = pd;
    g_aself[n * 4 + h] = lrelu(ps + pd + ael);
}

// ---------------- softmax (warp per node, atomic-free) ----------------
__global__ void softmax_kernel(int l, int N) {
    int wid = (blockIdx.x * blockDim.x + threadIdx.x) >> 5;
    int lane = threadIdx.x & 31;
    if (wid >= N) return;
    const int d = wid;
    const int start = g_rowptr[d];
    const int deg = g_degi[d];
    float4 ad = ((const float4*)g_adst)[d];
    float4 asf = ((const float4*)g_aself)[d];
    float4 m = asf;   // self-loop seeds the max
    const float4* aeB = (const float4*)g_ae[l];

    for (int j = lane; j < deg; j += 32) {
        int s = __ldg(g_csrc + start + j);
        float4 as = __ldg(((const float4*)g_asrc) + s);
        float4 ae = __ldg(aeB + start + j);
        float4 a;
        a.x = lrelu(as.x + ad.x + ae.x);
        a.y = lrelu(as.y + ad.y + ae.y);
        a.z = lrelu(as.z + ad.z + ae.z);
        a.w = lrelu(as.w + ad.w + ae.w);
        ((float4*)g_w)[start + j] = a;
        m.x = fmaxf(m.x, a.x); m.y = fmaxf(m.y, a.y);
        m.z = fmaxf(m.z, a.z); m.w = fmaxf(m.w, a.w);
    }
#pragma unroll
    for (int o = 16; o; o >>= 1) {
        m.x = fmaxf(m.x, __shfl_xor_sync(0xffffffffu, m.x, o));
        m.y = fmaxf(m.y, __shfl_xor_sync(0xffffffffu, m.y, o));
        m.z = fmaxf(m.z, __shfl_xor_sync(0xffffffffu, m.z, o));
        m.w = fmaxf(m.w, __shfl_xor_sync(0xffffffffu, m.w, o));
    }
    float4 den = make_float4(0.f, 0.f, 0.f, 0.f);
    for (int j = lane; j < deg; j += 32) {
        float4 a = ((const float4*)g_w)[start + j];
        a.x = __expf(a.x - m.x); a.y = __expf(a.y - m.y);
        a.z = __expf(a.z - m.z); a.w = __expf(a.w - m.w);
        ((float4*)g_w)[start + j] = a;
        den.x += a.x; den.y += a.y; den.z += a.z; den.w += a.w;
    }
#pragma unroll
    for (int o = 16; o; o >>= 1) {
        den.x += __shfl_xor_sync(0xffffffffu, den.x, o);
        den.y += __shfl_xor_sync(0xffffffffu, den.y, o);
        den.z += __shfl_xor_sync(0xffffffffu, den.z, o);
        den.w += __shfl_xor_sync(0xffffffffu, den.w, o);
    }
    if (lane == 0) {
        float4 ws;
        ws.x = __expf(asf.x - m.x); ws.y = __expf(asf.y - m.y);
        ws.z = __expf(asf.z - m.z); ws.w = __expf(asf.w - m.w);
        float4 rd;
        rd.x = 1.f / (den.x + ws.x + 1e-16f);
        rd.y = 1.f / (den.y + ws.y + 1e-16f);
        rd.z = 1.f / (den.z + ws.z + 1e-16f);
        rd.w = 1.f / (den.w + ws.w + 1e-16f);
        ((float4*)g_wself)[d] = ws;
        ((float4*)g_rden)[d] = rd;
    }
}

// ---------------- aggregate (warp per node, lanes = channels; no atomics) ----------------
__global__ void aggregate_kernel(const float* __restrict__ bias_conv, int l, int N) {
    int wid = (blockIdx.x * blockDim.x + threadIdx.x) >> 5;
    int lane = threadIdx.x & 31;
    if (wid >= N) return;
    const int d = wid;
    const int h = lane >> 3;
    const int start = g_rowptr[d];
    const int deg = g_degi[d];

    float ws = __ldg(g_wself + d * 4 + h);
    float rd = __ldg(g_rden + d * 4 + h);
    float4 acc = __ldg(((const float4*)g_xh) + (size_t)d * 32 + lane);
    acc.x *= ws; acc.y *= ws; acc.z *= ws; acc.w *= ws;

#pragma unroll 2
    for (int j = 0; j < deg; j++) {
        float w = __ldg(g_w + (size_t)(start + j) * 4 + h);
        int s = __ldg(g_csrc + start + j);
        float4 v = __ldg(((const float4*)g_xh) + (size_t)s * 32 + lane);
        acc.x += w * v.x; acc.y += w * v.y;
        acc.z += w * v.z; acc.w += w * v.w;
    }
    float4 b = __ldg(((const float4*)(bias_conv + l * 128)) + lane);
    float4 g;
    g.x = acc.x * rd + b.x; g.y = acc.y * rd + b.y;
    g.z = acc.z * rd + b.z; g.w = acc.w * rd + b.w;
    ((float4*)g_acc)[(size_t)d * 32 + lane] = g;
}

// ---------------- BN reduce ----------------
__global__ void bnreduce_kernel(int N) {
    int c = threadIdx.x;   // 128 channels
    float s1 = 0.f, s2 = 0.f;
    for (int n = blockIdx.x; n < N; n += gridDim.x) {
        float g = g_acc[(size_t)n * 128 + c];
        s1 += g; s2 += g * g;
    }
    atomicAdd(&g_bnsum[c], (double)s1);
    atomicAdd(&g_bnsq[c], (double)s2);
}

// ---------------- BN stats -> scale/shift ----------------
__global__ void bnstats_kernel(const float* __restrict__ gamma,
                               const float* __restrict__ beta, int l, int N) {
    int c = threadIdx.x;
    double mu = g_bnsum[c] / (double)N;
    double var = g_bnsq[c] / (double)N - mu * mu;
    float rstd = (float)rsqrt(var + 1e-5);
    float ga = gamma[l * 128 + c];
    g_bnscale[c] = ga * rstd;
    g_bnshift[c] = beta[l * 128 + c] - ga * (float)mu * rstd;
}

// ---------------- BN + relu + residual -> g_h ----------------
__global__ void node3_kernel(int N) {
    int idx = blockIdx.x * blockDim.x + threadIdx.x;
    if (idx >= N * 32) return;
    int q = idx & 31;
    float4 g = ((const float4*)g_acc)[idx];
    float4 hi = ((const float4*)g_h)[idx];
    float4 sc = ((const float4*)g_bnscale)[q];
    float4 sh = ((const float4*)g_bnshift)[q];
    float4 o;
    o.x = fmaxf(fmaf(g.x, sc.x, sh.x), 0.f) + hi.x;
    o.y = fmaxf(fmaf(g.y, sc.y, sh.y), 0.f) + hi.y;
    o.z = fmaxf(fmaf(g.z, sc.z, sh.z), 0.f) + hi.z;
    o.w = fmaxf(fmaf(g.w, sc.w, sh.w), 0.f) + hi.w;
    ((float4*)g_h)[idx] = o;
}

// ---------------- launcher ----------------
extern "C" void kernel_launch(void* const* d_in, const int* in_sizes, int n_in,
                              void* d_out, int out_size) {
    (void)n_in; (void)out_size;
    const float* x         = (const float*)d_in[0];
    const int*   ei        = (const int*)  d_in[1];
    const float* edge_attr = (const float*)d_in[2];
    const float* W_atom    = (const float*)d_in[3];
    const float* b_atom    = (const float*)d_in[4];
    const float* W_bond    = (const float*)d_in[5];
    const float* b_bond    = (const float*)d_in[6];
    const float* W_lin     = (const float*)d_in[7];
    const float* W_edge    = (const float*)d_in[8];
    const float* att_src   = (const float*)d_in[9];
    const float* att_dst   = (const float*)d_in[10];
    const float* att_edge  = (const float*)d_in[11];
    const float* bias_conv = (const float*)d_in[12];
    const float* bn_gamma  = (const float*)d_in[13];
    const float* bn_beta   = (const float*)d_in[14];
    const float* W_out     = (const float*)d_in[15];
    const float* b_out     = (const float*)d_in[16];
    float* out = (float*)d_out;

    const int N = in_sizes[0] / 64;
    const int E = in_sizes[1] / 2;
    const int nb = (N + SCAN_BLK - 1) / SCAN_BLK;

    const int smem128 = (128 * 128 + 64 * 132) * 4;
    const int smem64  = (64 * 128 + 64 * 68) * 4;
    cudaFuncSetAttribute(gemm_kernel<128>, cudaFuncAttributeMaxDynamicSharedMemorySize, smem128);
    cudaFuncSetAttribute(gemm_kernel<64>,  cudaFuncAttributeMaxDynamicSharedMemorySize, smem64);

    float* ph;  cudaGetSymbolAddress((void**)&ph,  g_h);
    float* pxh; cudaGetSymbolAddress((void**)&pxh, g_xh);

    // ---- preprocessing: deg/easum, folded consts, CSR counting sort ----
    prep_zero_kernel<<<(N * 16 + 255) / 256, 256>>>(N);
    consts_kernel<<<1, 128>>>(W_edge, att_edge, W_bond, b_bond);
    edge_prep_kernel<<<(E + 255) / 256, 256>>>(ei, edge_attr, E);
    scan_sum_kernel<<<nb, SCAN_BLK>>>(N);
    scan_mid_kernel<<<1, 32>>>(nb);
    scan_final_kernel<<<nb, SCAN_BLK>>>(N);
    scatter_kernel<<<(E + 255) / 256, 256>>>(ei, edge_attr, E);

    // ---- atom embedding ----
    gemm_kernel<64><<<(N + 63) / 64, 256, smem64>>>(x, W_atom, b_atom, ph, N);

    for (int l = 0; l < 3; l++) {
        gemm_kernel<128><<<(N + 63) / 64, 256, smem128>>>(ph, W_lin + l * 128 * 128, nullptr, pxh, N);
        node1_kernel<<<(N * 32 + 255) / 256, 256>>>(att_src, att_dst, l, N);
        softmax_kernel<<<(N * 32 + 255) / 256, 256>>>(l, N);
        aggregate_kernel<<<(N * 32 + 255) / 256, 256>>>(bias_conv, l, N);
        bnreduce_kernel<<<512, 128>>>(N);
        bnstats_kernel<<<1, 128>>>(bn_gamma, bn_beta, l, N);
        node3_kernel<<<(N * 32 + 255) / 256, 256>>>(N);
    }

    gemm_kernel<128><<<(N + 63) / 64, 256, smem128>>>(ph, W_out, b_out, out, N);
}

// round 10
// speedup vs baseline: 1.4327x; 1.1205x over previous
#include <cuda_runtime.h>
#include <math.h>

// ---------------- problem constants ----------------
#define HIDC 128
#define NMAX 50000
#define EMAX 600000
#define SCAN_BLK 512

// ---------------- device scratch ----------------
__device__ __align__(128) float g_h    [NMAX * HIDC];
__device__ __align__(128) float g_xh   [NMAX * HIDC];
__device__ __align__(128) float g_acc  [NMAX * HIDC];
__device__ __align__(128) float g_asrc [NMAX * 4];
__device__ __align__(128) float g_adst [NMAX * 4];
__device__ __align__(128) float g_aself[NMAX * 4];
__device__ __align__(128) float g_easum[NMAX * 16];
__device__ __align__(128) float g_M    [3 * 64];
__device__ __align__(128) float g_c    [3 * 4];
__device__ int   g_degi  [NMAX];
__device__ int   g_fill  [NMAX];
__device__ int   g_rowptr[NMAX];
__device__ int   g_bsum  [256];
__device__ __align__(128) int   g_csrc[EMAX];
__device__ __align__(128) float g_ae  [3][EMAX * 4];   // folded edge logits, CSR order
__device__ __align__(128) float g_w   [EMAX * 4];      // per-edge softmax scratch
__device__ double g_bnsum[HIDC];
__device__ double g_bnsq [HIDC];
__device__ __align__(128) float g_bnscale[HIDC];
__device__ __align__(128) float g_bnshift[HIDC];

// ---------------- helpers ----------------
__device__ __forceinline__ void redAdd4(float* addr, float4 v) {
    asm volatile("red.global.add.v4.f32 [%0], {%1, %2, %3, %4};"
                 :: "l"(addr), "f"(v.x), "f"(v.y), "f"(v.z), "f"(v.w) : "memory");
}
__device__ __forceinline__ float lrelu(float a) { return a > 0.f ? a : 0.2f * a; }

__device__ __forceinline__ unsigned long long pack2(float a) {
    unsigned long long r;
    asm("mov.b64 %0, {%1, %1};" : "=l"(r) : "r"(__float_as_uint(a)));
    return r;
}
__device__ __forceinline__ float2 unpack2(unsigned long long v) {
    unsigned int lo, hi;
    asm("mov.b64 {%0, %1}, %2;" : "=r"(lo), "=r"(hi) : "l"(v));
    return make_float2(__uint_as_float(lo), __uint_as_float(hi));
}
#define FMA2(acc, a2, b2) \
    asm("fma.rn.f32x2 %0, %1, %2, %0;" : "+l"(acc) : "l"(a2), "l"(b2))

__device__ __forceinline__ float sel4(float4 v, int h) {
    float ab = (h & 1) ? v.y : v.x;
    float cd = (h & 1) ? v.w : v.z;
    return (h & 2) ? cd : ab;
}

// ---------------- prep: zeros ----------------
__global__ void prep_zero_kernel(int N) {
    int i = blockIdx.x * blockDim.x + threadIdx.x;
    if (i < N)      { g_degi[i] = 0; g_fill[i] = 0; }
    if (i < N * 16) g_easum[i] = 0.f;
}

// ---------------- per-layer folded constants: M = W_bond @ Ve, c = b_bond . Ve ----------------
__global__ void consts_kernel(const float* __restrict__ W_edge,
                              const float* __restrict__ att_edge,
                              const float* __restrict__ W_bond,
                              const float* __restrict__ b_bond) {
    __shared__ float Ve[128 * 4];
    int t = threadIdx.x; // 128 threads
    for (int l = 0; l < 3; l++) {
        const float* We = W_edge + l * 128 * 128 + t * 128;
        const float* ae = att_edge + l * 128;
        float v0 = 0.f, v1 = 0.f, v2 = 0.f, v3 = 0.f;
        for (int d = 0; d < 32; d++) {
            v0 += We[d]      * ae[d];
            v1 += We[32 + d] * ae[32 + d];
            v2 += We[64 + d] * ae[64 + d];
            v3 += We[96 + d] * ae[96 + d];
        }
        Ve[t * 4 + 0] = v0; Ve[t * 4 + 1] = v1; Ve[t * 4 + 2] = v2; Ve[t * 4 + 3] = v3;
        __syncthreads();
        if (t < 16) {
            float m0 = 0.f, m1 = 0.f, m2 = 0.f, m3 = 0.f;
            for (int k = 0; k < 128; k++) {
                float w = W_bond[t * 128 + k];
                m0 += w * Ve[k * 4 + 0]; m1 += w * Ve[k * 4 + 1];
                m2 += w * Ve[k * 4 + 2]; m3 += w * Ve[k * 4 + 3];
            }
            g_M[l * 64 + t * 4 + 0] = m0; g_M[l * 64 + t * 4 + 1] = m1;
            g_M[l * 64 + t * 4 + 2] = m2; g_M[l * 64 + t * 4 + 3] = m3;
        } else if (t < 20) {
            int h = t - 16;
            float cc = 0.f;
            for (int k = 0; k < 128; k++) cc += b_bond[k] * Ve[k * 4 + h];
            g_c[l * 4 + h] = cc;
        }
        __syncthreads();
    }
}

// ---------------- degree + segment_sum(edge_attr) over dst ----------------
__global__ void edge_prep_kernel(const int* __restrict__ ei,
                                 const float* __restrict__ edge_attr, int E) {
    int e = blockIdx.x * blockDim.x + threadIdx.x;
    if (e >= E) return;
    int d = ei[E + e];
    atomicAdd(&g_degi[d], 1);
    const float4* ev = ((const float4*)edge_attr) + e * 4;
#pragma unroll
    for (int q = 0; q < 4; q++) redAdd4(&g_easum[d * 16 + 4 * q], ev[q]);
}

// ---------------- exclusive scan of degi -> rowptr ----------------
__global__ void scan_sum_kernel(int N) {
    __shared__ int sh[16];
    int b = blockIdx.x, t = threadIdx.x;
    int i = b * SCAN_BLK + t;
    int v = (i < N) ? g_degi[i] : 0;
#pragma unroll
    for (int o = 16; o; o >>= 1) v += __shfl_xor_sync(0xffffffffu, v, o);
    if ((t & 31) == 0) sh[t >> 5] = v;
    __syncthreads();
    if (t < 16) {
        int s = sh[t];
#pragma unroll
        for (int o = 8; o; o >>= 1) s += __shfl_xor_sync(0xffffu, s, o);
        if (t == 0) g_bsum[b] = s;
    }
}
__global__ void scan_mid_kernel(int nb) {
    if (threadIdx.x == 0) {
        int acc = 0;
        for (int b = 0; b < nb; b++) { int v = g_bsum[b]; g_bsum[b] = acc; acc += v; }
    }
}
__global__ void scan_final_kernel(int N) {
    __shared__ int wsum[16];
    int b = blockIdx.x, t = threadIdx.x;
    int i = b * SCAN_BLK + t;
    int v = (i < N) ? g_degi[i] : 0;
    int x = v;
#pragma unroll
    for (int o = 1; o < 32; o <<= 1) {
        int y = __shfl_up_sync(0xffffffffu, x, o);
        if ((t & 31) >= o) x += y;
    }
    if ((t & 31) == 31) wsum[t >> 5] = x;
    __syncthreads();
    if (t == 0) {
        int acc = 0;
        for (int w = 0; w < 16; w++) { int s = wsum[w]; wsum[w] = acc; acc += s; }
    }
    __syncthreads();
    if (i < N) g_rowptr[i] = x - v + wsum[t >> 5] + g_bsum[b];
}

// ---------------- counting-sort scatter: csr_src + folded edge logits per layer ----------------
__global__ void scatter_kernel(const int* __restrict__ ei,
                               const float* __restrict__ edge_attr, int E) {
    __shared__ float Ms[192];
    __shared__ float Cs[12];
    int t = threadIdx.x;
    if (t < 192) Ms[t] = g_M[t];
    if (t < 12)  Cs[t] = g_c[t];
    __syncthreads();
    int e = blockIdx.x * blockDim.x + t;
    if (e >= E) return;
    int s = ei[e], d = ei[E + e];
    int pos = g_rowptr[d] + atomicAdd(&g_fill[d], 1);
    g_csrc[pos] = s;
    float ev[16];
    const float4* ep = ((const float4*)edge_attr) + e * 4;
#pragma unroll
    for (int q = 0; q < 4; q++) {
        float4 v = ep[q];
        ev[4 * q] = v.x; ev[4 * q + 1] = v.y; ev[4 * q + 2] = v.z; ev[4 * q + 3] = v.w;
    }
#pragma unroll
    for (int l = 0; l < 3; l++) {
        float a0 = Cs[l * 4 + 0], a1 = Cs[l * 4 + 1], a2 = Cs[l * 4 + 2], a3 = Cs[l * 4 + 3];
#pragma unroll
        for (int k = 0; k < 16; k++) {
            float v = ev[k];
            a0 += v * Ms[l * 64 + k * 4 + 0]; a1 += v * Ms[l * 64 + k * 4 + 1];
            a2 += v * Ms[l * 64 + k * 4 + 2]; a3 += v * Ms[l * 64 + k * 4 + 3];
        }
        ((float4*)g_ae[l])[pos] = make_float4(a0, a1, a2, a3);
    }
}

// ---------------- GEMM: C[M,128] = A'[M,K] @ B[K,128] (+ bias) ----------------
// FUSEBN: A' = relu(A*bnscale + bnshift) + hres  (BN+ReLU+residual fused into the
// A-load; new h is also written back to hres). Uses packed fma.rn.f32x2.
template <int K, bool FUSEBN>
__global__ __launch_bounds__(256) void gemm_kernel(const float* __restrict__ A,
                                                   const float* __restrict__ B,
                                                   const float* __restrict__ bias,
                                                   float* __restrict__ C,
                                                   float* __restrict__ hres,
                                                   int M) {
    constexpr int AST = K + 4;  // padded row stride (floats), 16B-aligned
    extern __shared__ float sm[];
    float* Bs = sm;               // K*128
    float* As = sm + K * 128;     // 64*AST
    const int t = threadIdx.x;
    const int row0 = blockIdx.x * 64;

    for (int idx = t; idx < K * 32; idx += 256)
        ((float4*)Bs)[idx] = ((const float4*)B)[idx];

    constexpr int KQ = K / 4;
    for (int idx = t; idx < 64 * KQ; idx += 256) {
        int r = idx / KQ, q = idx - r * KQ;
        int grow = row0 + r;
        float4 o = make_float4(0.f, 0.f, 0.f, 0.f);
        if (grow < M) {
            float4 v = ((const float4*)(A + (size_t)grow * K))[q];
            if (FUSEBN) {
                float4 hv = ((const float4*)(hres + (size_t)grow * K))[q];
                float4 sc = __ldg(((const float4*)g_bnscale) + q);
                float4 sh = __ldg(((const float4*)g_bnshift) + q);
                o.x = fmaxf(fmaf(v.x, sc.x, sh.x), 0.f) + hv.x;
                o.y = fmaxf(fmaf(v.y, sc.y, sh.y), 0.f) + hv.y;
                o.z = fmaxf(fmaf(v.z, sc.z, sh.z), 0.f) + hv.z;
                o.w = fmaxf(fmaf(v.w, sc.w, sh.w), 0.f) + hv.w;
                ((float4*)(hres + (size_t)grow * K))[q] = o;
            } else {
                o = v;
            }
        }
        *(float4*)(As + r * AST + 4 * q) = o;
    }
    __syncthreads();

    const int j = t & 15;   // cols 8j..8j+7
    const int i = t >> 4;   // rows 4i..4i+3
    unsigned long long acc2[4][4] = {};   // 4 rows x 4 packed col-pairs

    const float* aBase = As + (4 * i) * AST;
    const ulonglong2* BsP = (const ulonglong2*)Bs;   // 32 ulonglong2 per row
#pragma unroll 2
    for (int k4 = 0; k4 < K / 4; k4++) {
        float4 av[4];
#pragma unroll
        for (int r = 0; r < 4; r++)
            av[r] = *(const float4*)(aBase + r * AST + 4 * k4);
#pragma unroll
        for (int kk = 0; kk < 4; kk++) {
            int k = 4 * k4 + kk;
            ulonglong2 b01 = BsP[k * 32 + 2 * j];
            ulonglong2 b23 = BsP[k * 32 + 2 * j + 1];
#pragma unroll
            for (int r = 0; r < 4; r++) {
                unsigned long long ap = pack2(((const float*)&av[r])[kk]);
                FMA2(acc2[r][0], ap, b01.x);
                FMA2(acc2[r][1], ap, b01.y);
                FMA2(acc2[r][2], ap, b23.x);
                FMA2(acc2[r][3], ap, b23.y);
            }
        }
    }

    float4 bb0 = make_float4(0.f, 0.f, 0.f, 0.f), bb1 = bb0;
    if (bias) { bb0 = ((const float4*)bias)[2 * j]; bb1 = ((const float4*)bias)[2 * j + 1]; }
#pragma unroll
    for (int r = 0; r < 4; r++) {
        int grow = row0 + 4 * i + r;
        if (grow >= M) continue;
        float2 p0 = unpack2(acc2[r][0]);
        float2 p1 = unpack2(acc2[r][1]);
        float2 p2 = unpack2(acc2[r][2]);
        float2 p3 = unpack2(acc2[r][3]);
        float4* cp = (float4*)(C + (size_t)grow * 128);
        cp[2 * j]     = make_float4(p0.x + bb0.x, p0.y + bb0.y, p1.x + bb0.z, p1.y + bb0.w);
        cp[2 * j + 1] = make_float4(p2.x + bb1.x, p2.y + bb1.y, p3.x + bb1.z, p3.y + bb1.w);
    }
}

// ---------------- node pass 1: a_src/a_dst/a_self ----------------
__global__ void node1_kernel(const float* __restrict__ att_src,
                             const float* __restrict__ att_dst,
                             int l, int N) {
    if (blockIdx.x == 0 && threadIdx.x < 128) {
        g_bnsum[threadIdx.x] = 0.0;
        g_bnsq[threadIdx.x] = 0.0;
    }
    int gt = blockIdx.x * blockDim.x + threadIdx.x;
    int nRaw = gt >> 5;
    bool valid = nRaw < N;
    int n = valid ? nRaw : (N - 1);
    int lane = gt & 31;

    float4 xv = ((const float4*)g_xh)[n * 32 + lane];
    float4 sv = ((const float4*)(att_src + l * 128))[lane];
    float4 dv = ((const float4*)(att_dst + l * 128))[lane];
    float ps = xv.x * sv.x + xv.y * sv.y + xv.z * sv.z + xv.w * sv.w;
    float pd = xv.x * dv.x + xv.y * dv.y + xv.z * dv.z + xv.w * dv.w;
#pragma unroll
    for (int off = 4; off > 0; off >>= 1) {
        ps += __shfl_xor_sync(0xffffffffu, ps, off);
        pd += __shfl_xor_sync(0xffffffffu, pd, off);
    }
    if (!valid || (lane & 7)) return;
    int h = lane >> 3;
    float ael = 0.f;
    float degv = (float)g_degi[n];
    if (degv > 0.f) {
        const float* es = g_easum + n * 16;
        const float* Mh = g_M + l * 64 + h;
        float sacc = 0.f;
#pragma unroll
        for (int k = 0; k < 16; k++) sacc += es[k] * Mh[k * 4];
        ael = sacc / degv + g_c[l * 4 + h];
    }
    g_asrc[n * 4 + h] = ps;
    g_adst[n * 4 + h] = pd;
    g_aself[n * 4 + h] = lrelu(ps + pd + ael);
}

// ---------------- fused GAT: softmax + aggregate + BN partial sums ----------------
__global__ __launch_bounds__(256) void gat_kernel(const float* __restrict__ bias_conv,
                                                  int l, int N) {
    const int lane = threadIdx.x & 31;
    const int wLocal = threadIdx.x >> 5;            // 0..7
    const int warpsTotal = (gridDim.x * blockDim.x) >> 5;
    const int h = lane >> 3;
    const float4* aeB = (const float4*)g_ae[l];
    const float4 bq = __ldg(((const float4*)(bias_conv + l * 128)) + lane);

    float bs1[4] = {0.f, 0.f, 0.f, 0.f};
    float bs2[4] = {0.f, 0.f, 0.f, 0.f};

    for (int d = (blockIdx.x * blockDim.x + threadIdx.x) >> 5; d < N; d += warpsTotal) {
        const int start = __ldg(g_rowptr + d);
        const int deg = __ldg(g_degi + d);
        float4 ad = __ldg(((const float4*)g_adst) + d);
        float4 asf = __ldg(((const float4*)g_aself) + d);
        float4 m = asf;   // self-loop seeds the max

        for (int jj = lane; jj < deg; jj += 32) {
            int s = __ldg(g_csrc + start + jj);
            float4 as = __ldg(((const float4*)g_asrc) + s);
            float4 ae = __ldg(aeB + start + jj);
            float4 a;
            a.x = lrelu(as.x + ad.x + ae.x);
            a.y = lrelu(as.y + ad.y + ae.y);
            a.z = lrelu(as.z + ad.z + ae.z);
            a.w = lrelu(as.w + ad.w + ae.w);
            ((float4*)g_w)[start + jj] = a;
            m.x = fmaxf(m.x, a.x); m.y = fmaxf(m.y, a.y);
            m.z = fmaxf(m.z, a.z); m.w = fmaxf(m.w, a.w);
        }
#pragma unroll
        for (int o = 16; o; o >>= 1) {
            m.x = fmaxf(m.x, __shfl_xor_sync(0xffffffffu, m.x, o));
            m.y = fmaxf(m.y, __shfl_xor_sync(0xffffffffu, m.y, o));
            m.z = fmaxf(m.z, __shfl_xor_sync(0xffffffffu, m.z, o));
            m.w = fmaxf(m.w, __shfl_xor_sync(0xffffffffu, m.w, o));
        }
        float4 den = make_float4(0.f, 0.f, 0.f, 0.f);
        for (int jj = lane; jj < deg; jj += 32) {
            float4 a = ((const float4*)g_w)[start + jj];
            a.x = __expf(a.x - m.x); a.y = __expf(a.y - m.y);
            a.z = __expf(a.z - m.z); a.w = __expf(a.w - m.w);
            ((float4*)g_w)[start + jj] = a;
            den.x += a.x; den.y += a.y; den.z += a.z; den.w += a.w;
        }
#pragma unroll
        for (int o = 16; o; o >>= 1) {
            den.x += __shfl_xor_sync(0xffffffffu, den.x, o);
            den.y += __shfl_xor_sync(0xffffffffu, den.y, o);
            den.z += __shfl_xor_sync(0xffffffffu, den.z, o);
            den.w += __shfl_xor_sync(0xffffffffu, den.w, o);
        }
        __syncwarp();   // g_w stores visible to cross-lane reads below

        // aggregate phase: lane = channel quad (channels 4*lane..4*lane+3, head h)
        float asfh = sel4(asf, h), mh = sel4(m, h), denh = sel4(den, h);
        float wsh = __expf(asfh - mh);
        float rdh = 1.f / (denh + wsh + 1e-16f);

        float4 acc = __ldg(((const float4*)g_xh) + (size_t)d * 32 + lane);
        acc.x *= wsh; acc.y *= wsh; acc.z *= wsh; acc.w *= wsh;
#pragma unroll 2
        for (int jj = 0; jj < deg; jj++) {
            float w = __ldg(g_w + (size_t)(start + jj) * 4 + h);
            int s = __ldg(g_csrc + start + jj);
            float4 v = __ldg(((const float4*)g_xh) + (size_t)s * 32 + lane);
            acc.x += w * v.x; acc.y += w * v.y;
            acc.z += w * v.z; acc.w += w * v.w;
        }
        float4 g;
        g.x = acc.x * rdh + bq.x; g.y = acc.y * rdh + bq.y;
        g.z = acc.z * rdh + bq.z; g.w = acc.w * rdh + bq.w;
        ((float4*)g_acc)[(size_t)d * 32 + lane] = g;

        bs1[0] += g.x; bs1[1] += g.y; bs1[2] += g.z; bs1[3] += g.w;
        bs2[0] += g.x * g.x; bs2[1] += g.y * g.y;
        bs2[2] += g.z * g.z; bs2[3] += g.w * g.w;
    }

    // block-level BN reduction (8 warps x 128 channels)
    __shared__ float sred[8][128];
#pragma unroll
    for (int q = 0; q < 4; q++) sred[wLocal][4 * lane + q] = bs1[q];
    __syncthreads();
    if (threadIdx.x < 128) {
        float s = 0.f;
#pragma unroll
        for (int w = 0; w < 8; w++) s += sred[w][threadIdx.x];
        atomicAdd(&g_bnsum[threadIdx.x], (double)s);
    }
    __syncthreads();
#pragma unroll
    for (int q = 0; q < 4; q++) sred[wLocal][4 * lane + q] = bs2[q];
    __syncthreads();
    if (threadIdx.x < 128) {
        float s = 0.f;
#pragma unroll
        for (int w = 0; w < 8; w++) s += sred[w][threadIdx.x];
        atomicAdd(&g_bnsq[threadIdx.x], (double)s);
    }
}

// ---------------- BN stats -> scale/shift ----------------
__global__ void bnstats_kernel(const float* __restrict__ gamma,
                               const float* __restrict__ beta, int l, int N) {
    int c = threadIdx.x;
    double mu = g_bnsum[c] / (double)N;
    double var = g_bnsq[c] / (double)N - mu * mu;
    float rstd = (float)rsqrt(var + 1e-5);
    float ga = gamma[l * 128 + c];
    g_bnscale[c] = ga * rstd;
    g_bnshift[c] = beta[l * 128 + c] - ga * (float)mu * rstd;
}

// ---------------- launcher ----------------
extern "C" void kernel_launch(void* const* d_in, const int* in_sizes, int n_in,
                              void* d_out, int out_size) {
    (void)n_in; (void)out_size;
    const float* x         = (const float*)d_in[0];
    const int*   ei        = (const int*)  d_in[1];
    const float* edge_attr = (const float*)d_in[2];
    const float* W_atom    = (const float*)d_in[3];
    const float* b_atom    = (const float*)d_in[4];
    const float* W_bond    = (const float*)d_in[5];
    const float* b_bond    = (const float*)d_in[6];
    const float* W_lin     = (const float*)d_in[7];
    const float* W_edge    = (const float*)d_in[8];
    const float* att_src   = (const float*)d_in[9];
    const float* att_dst   = (const float*)d_in[10];
    const float* att_edge  = (const float*)d_in[11];
    const float* bias_conv = (const float*)d_in[12];
    const float* bn_gamma  = (const float*)d_in[13];
    const float* bn_beta   = (const float*)d_in[14];
    const float* W_out     = (const float*)d_in[15];
    const float* b_out     = (const float*)d_in[16];
    float* out = (float*)d_out;

    const int N = in_sizes[0] / 64;
    const int E = in_sizes[1] / 2;
    const int nb = (N + SCAN_BLK - 1) / SCAN_BLK;

    const int smem128 = (128 * 128 + 64 * 132) * 4;
    const int smem64  = (64 * 128 + 64 * 68) * 4;
    cudaFuncSetAttribute(gemm_kernel<128, false>, cudaFuncAttributeMaxDynamicSharedMemorySize, smem128);
    cudaFuncSetAttribute(gemm_kernel<128, true>,  cudaFuncAttributeMaxDynamicSharedMemorySize, smem128);
    cudaFuncSetAttribute(gemm_kernel<64, false>,  cudaFuncAttributeMaxDynamicSharedMemorySize, smem64);

    float* ph;   cudaGetSymbolAddress((void**)&ph,   g_h);
    float* pxh;  cudaGetSymbolAddress((void**)&pxh,  g_xh);
    float* pacc; cudaGetSymbolAddress((void**)&pacc, g_acc);

    // ---- preprocessing: deg/easum, folded consts, CSR counting sort ----
    prep_zero_kernel<<<(N * 16 + 255) / 256, 256>>>(N);
    consts_kernel<<<1, 128>>>(W_edge, att_edge, W_bond, b_bond);
    edge_prep_kernel<<<(E + 255) / 256, 256>>>(ei, edge_attr, E);
    scan_sum_kernel<<<nb, SCAN_BLK>>>(N);
    scan_mid_kernel<<<1, 32>>>(nb);
    scan_final_kernel<<<nb, SCAN_BLK>>>(N);
    scatter_kernel<<<(E + 255) / 256, 256>>>(ei, edge_attr, E);

    // ---- atom embedding ----
    gemm_kernel<64, false><<<(N + 63) / 64, 256, smem64>>>(x, W_atom, b_atom, ph, nullptr, N);

    for (int l = 0; l < 3; l++) {
        if (l == 0)
            gemm_kernel<128, false><<<(N + 63) / 64, 256, smem128>>>(
                ph, W_lin, nullptr, pxh, nullptr, N);
        else
            gemm_kernel<128, true><<<(N + 63) / 64, 256, smem128>>>(
                pacc, W_lin + l * 128 * 128, nullptr, pxh, ph, N);
        node1_kernel<<<(N * 32 + 255) / 256, 256>>>(att_src, att_dst, l, N);
        gat_kernel<<<1184, 256>>>(bias_conv, l, N);
        bnstats_kernel<<<1, 128>>>(bn_gamma, bn_beta, l, N);
    }

    // output projection with fused BN+ReLU+residual of layer 3
    gemm_kernel<128, true><<<(N + 63) / 64, 256, smem128>>>(
        pacc, W_out, b_out, out, ph, N);
}

// round 11
// speedup vs baseline: 1.4720x; 1.0274x over previous
#include <cuda_runtime.h>
#include <math.h>

// ---------------- problem constants ----------------
#define HIDC 128
#define NMAX 50000
#define EMAX 600000
#define SCAN_BLK 512

// ---------------- device scratch ----------------
__device__ __align__(128) float g_h    [NMAX * HIDC];
__device__ __align__(128) float g_xh   [NMAX * HIDC];
__device__ __align__(128) float g_acc  [NMAX * HIDC];
__device__ __align__(128) float g_asrc [NMAX * 4];
__device__ __align__(128) float g_adst [NMAX * 4];
__device__ __align__(128) float g_aself[NMAX * 4];
__device__ __align__(128) float g_easum[NMAX * 16];
__device__ __align__(128) float g_M    [3 * 64];
__device__ __align__(128) float g_c    [3 * 4];
__device__ int   g_degi  [NMAX];
__device__ int   g_fill  [NMAX];
__device__ int   g_rowptr[NMAX];
__device__ int   g_bsum  [256];
__device__ __align__(128) int   g_csrc[EMAX];
__device__ __align__(128) float g_ae  [3][EMAX * 4];   // folded edge logits, CSR order
__device__ __align__(128) float g_w   [EMAX * 4];      // fallback scratch (deg>64 only)
__device__ double g_bnsum[HIDC];
__device__ double g_bnsq [HIDC];
__device__ __align__(128) float g_bnscale[HIDC];
__device__ __align__(128) float g_bnshift[HIDC];

// ---------------- helpers ----------------
__device__ __forceinline__ void redAdd4(float* addr, float4 v) {
    asm volatile("red.global.add.v4.f32 [%0], {%1, %2, %3, %4};"
                 :: "l"(addr), "f"(v.x), "f"(v.y), "f"(v.z), "f"(v.w) : "memory");
}
__device__ __forceinline__ float lrelu(float a) { return a > 0.f ? a : 0.2f * a; }

__device__ __forceinline__ unsigned long long pack2(float a) {
    unsigned long long r;
    asm("mov.b64 %0, {%1, %1};" : "=l"(r) : "r"(__float_as_uint(a)));
    return r;
}
__device__ __forceinline__ float2 unpack2(unsigned long long v) {
    unsigned int lo, hi;
    asm("mov.b64 {%0, %1}, %2;" : "=r"(lo), "=r"(hi) : "l"(v));
    return make_float2(__uint_as_float(lo), __uint_as_float(hi));
}
#define FMA2(acc, a2, b2) \
    asm("fma.rn.f32x2 %0, %1, %2, %0;" : "+l"(acc) : "l"(a2), "l"(b2))

__device__ __forceinline__ float sel4(float4 v, int h) {
    float ab = (h & 1) ? v.y : v.x;
    float cd = (h & 1) ? v.w : v.z;
    return (h & 2) ? cd : ab;
}
__device__ __forceinline__ float4 fmax4(float4 a, float4 b) {
    return make_float4(fmaxf(a.x, b.x), fmaxf(a.y, b.y), fmaxf(a.z, b.z), fmaxf(a.w, b.w));
}

// ---------------- prep: zeros ----------------
__global__ void prep_zero_kernel(int N) {
    int i = blockIdx.x * blockDim.x + threadIdx.x;
    if (i < N)      { g_degi[i] = 0; g_fill[i] = 0; }
    if (i < N * 16) g_easum[i] = 0.f;
    if (i < 128)    { g_bnsum[i] = 0.0; g_bnsq[i] = 0.0; }
}

// ---------------- per-layer folded constants: M = W_bond @ Ve, c = b_bond . Ve ----------------
__global__ void consts_kernel(const float* __restrict__ W_edge,
                              const float* __restrict__ att_edge,
                              const float* __restrict__ W_bond,
                              const float* __restrict__ b_bond) {
    __shared__ float Ve[128 * 4];
    int t = threadIdx.x; // 128 threads
    for (int l = 0; l < 3; l++) {
        const float* We = W_edge + l * 128 * 128 + t * 128;
        const float* ae = att_edge + l * 128;
        float v0 = 0.f, v1 = 0.f, v2 = 0.f, v3 = 0.f;
        for (int d = 0; d < 32; d++) {
            v0 += We[d]      * ae[d];
            v1 += We[32 + d] * ae[32 + d];
            v2 += We[64 + d] * ae[64 + d];
            v3 += We[96 + d] * ae[96 + d];
        }
        Ve[t * 4 + 0] = v0; Ve[t * 4 + 1] = v1; Ve[t * 4 + 2] = v2; Ve[t * 4 + 3] = v3;
        __syncthreads();
        if (t < 16) {
            float m0 = 0.f, m1 = 0.f, m2 = 0.f, m3 = 0.f;
            for (int k = 0; k < 128; k++) {
                float w = W_bond[t * 128 + k];
                m0 += w * Ve[k * 4 + 0]; m1 += w * Ve[k * 4 + 1];
                m2 += w * Ve[k * 4 + 2]; m3 += w * Ve[k * 4 + 3];
            }
            g_M[l * 64 + t * 4 + 0] = m0; g_M[l * 64 + t * 4 + 1] = m1;
            g_M[l * 64 + t * 4 + 2] = m2; g_M[l * 64 + t * 4 + 3] = m3;
        } else if (t < 20) {
            int h = t - 16;
            float cc = 0.f;
            for (int k = 0; k < 128; k++) cc += b_bond[k] * Ve[k * 4 + h];
            g_c[l * 4 + h] = cc;
        }
        __syncthreads();
    }
}

// ---------------- degree + segment_sum(edge_attr) over dst ----------------
__global__ void edge_prep_kernel(const int* __restrict__ ei,
                                 const float* __restrict__ edge_attr, int E) {
    int e = blockIdx.x * blockDim.x + threadIdx.x;
    if (e >= E) return;
    int d = ei[E + e];
    atomicAdd(&g_degi[d], 1);
    const float4* ev = ((const float4*)edge_attr) + e * 4;
#pragma unroll
    for (int q = 0; q < 4; q++) redAdd4(&g_easum[d * 16 + 4 * q], ev[q]);
}

// ---------------- exclusive scan of degi -> rowptr ----------------
__global__ void scan_sum_kernel(int N) {
    __shared__ int sh[16];
    int b = blockIdx.x, t = threadIdx.x;
    int i = b * SCAN_BLK + t;
    int v = (i < N) ? g_degi[i] : 0;
#pragma unroll
    for (int o = 16; o; o >>= 1) v += __shfl_xor_sync(0xffffffffu, v, o);
    if ((t & 31) == 0) sh[t >> 5] = v;
    __syncthreads();
    if (t < 16) {
        int s = sh[t];
#pragma unroll
        for (int o = 8; o; o >>= 1) s += __shfl_xor_sync(0xffffu, s, o);
        if (t == 0) g_bsum[b] = s;
    }
}
__global__ void scan_mid_kernel(int nb) {
    if (threadIdx.x == 0) {
        int acc = 0;
        for (int b = 0; b < nb; b++) { int v = g_bsum[b]; g_bsum[b] = acc; acc += v; }
    }
}
__global__ void scan_final_kernel(int N) {
    __shared__ int wsum[16];
    int b = blockIdx.x, t = threadIdx.x;
    int i = b * SCAN_BLK + t;
    int v = (i < N) ? g_degi[i] : 0;
    int x = v;
#pragma unroll
    for (int o = 1; o < 32; o <<= 1) {
        int y = __shfl_up_sync(0xffffffffu, x, o);
        if ((t & 31) >= o) x += y;
    }
    if ((t & 31) == 31) wsum[t >> 5] = x;
    __syncthreads();
    if (t == 0) {
        int acc = 0;
        for (int w = 0; w < 16; w++) { int s = wsum[w]; wsum[w] = acc; acc += s; }
    }
    __syncthreads();
    if (i < N) g_rowptr[i] = x - v + wsum[t >> 5] + g_bsum[b];
}

// ---------------- counting-sort scatter: csr_src + folded edge logits per layer ----------------
__global__ void scatter_kernel(const int* __restrict__ ei,
                               const float* __restrict__ edge_attr, int E) {
    __shared__ float Ms[192];
    __shared__ float Cs[12];
    int t = threadIdx.x;
    if (t < 192) Ms[t] = g_M[t];
    if (t < 12)  Cs[t] = g_c[t];
    __syncthreads();
    int e = blockIdx.x * blockDim.x + t;
    if (e >= E) return;
    int s = ei[e], d = ei[E + e];
    int pos = g_rowptr[d] + atomicAdd(&g_fill[d], 1);
    g_csrc[pos] = s;
    float ev[16];
    const float4* ep = ((const float4*)edge_attr) + e * 4;
#pragma unroll
    for (int q = 0; q < 4; q++) {
        float4 v = ep[q];
        ev[4 * q] = v.x; ev[4 * q + 1] = v.y; ev[4 * q + 2] = v.z; ev[4 * q + 3] = v.w;
    }
#pragma unroll
    for (int l = 0; l < 3; l++) {
        float a0 = Cs[l * 4 + 0], a1 = Cs[l * 4 + 1], a2 = Cs[l * 4 + 2], a3 = Cs[l * 4 + 3];
#pragma unroll
        for (int k = 0; k < 16; k++) {
            float v = ev[k];
            a0 += v * Ms[l * 64 + k * 4 + 0]; a1 += v * Ms[l * 64 + k * 4 + 1];
            a2 += v * Ms[l * 64 + k * 4 + 2]; a3 += v * Ms[l * 64 + k * 4 + 3];
        }
        ((float4*)g_ae[l])[pos] = make_float4(a0, a1, a2, a3);
    }
}

// ---------------- GEMM: C[M,128] = A'[M,K] @ B[K,128] (+ bias) ----------------
// FUSEBN: A' = relu(A*bnscale + bnshift) + hres, new h written back to hres.
// ATT:    epilogue also computes a_src/a_dst/a_self per (node, head) from C.
template <int K, bool FUSEBN, bool ATT>
__global__ __launch_bounds__(256) void gemm_kernel(const float* __restrict__ A,
                                                   const float* __restrict__ B,
                                                   const float* __restrict__ bias,
                                                   float* __restrict__ C,
                                                   float* __restrict__ hres,
                                                   const float* __restrict__ att_src,
                                                   const float* __restrict__ att_dst,
                                                   int l, int M) {
    constexpr int AST = K + 4;  // padded row stride (floats), 16B-aligned
    extern __shared__ float sm[];
    float* Bs = sm;               // K*128
    float* As = sm + K * 128;     // 64*AST
    const int t = threadIdx.x;
    const int row0 = blockIdx.x * 64;

    for (int idx = t; idx < K * 32; idx += 256)
        ((float4*)Bs)[idx] = ((const float4*)B)[idx];

    constexpr int KQ = K / 4;
    for (int idx = t; idx < 64 * KQ; idx += 256) {
        int r = idx / KQ, q = idx - r * KQ;
        int grow = row0 + r;
        float4 o = make_float4(0.f, 0.f, 0.f, 0.f);
        if (grow < M) {
            float4 v = ((const float4*)(A + (size_t)grow * K))[q];
            if (FUSEBN) {
                float4 hv = ((const float4*)(hres + (size_t)grow * K))[q];
                float4 sc = __ldg(((const float4*)g_bnscale) + q);
                float4 sh = __ldg(((const float4*)g_bnshift) + q);
                o.x = fmaxf(fmaf(v.x, sc.x, sh.x), 0.f) + hv.x;
                o.y = fmaxf(fmaf(v.y, sc.y, sh.y), 0.f) + hv.y;
                o.z = fmaxf(fmaf(v.z, sc.z, sh.z), 0.f) + hv.z;
                o.w = fmaxf(fmaf(v.w, sc.w, sh.w), 0.f) + hv.w;
                ((float4*)(hres + (size_t)grow * K))[q] = o;
            } else {
                o = v;
            }
        }
        *(float4*)(As + r * AST + 4 * q) = o;
    }
    __syncthreads();

    const int j = t & 15;   // cols 8j..8j+7
    const int i = t >> 4;   // rows 4i..4i+3
    unsigned long long acc2[4][4] = {};   // 4 rows x 4 packed col-pairs

    const float* aBase = As + (4 * i) * AST;
    const ulonglong2* BsP = (const ulonglong2*)Bs;   // 32 ulonglong2 per row
#pragma unroll 2
    for (int k4 = 0; k4 < K / 4; k4++) {
        float4 av[4];
#pragma unroll
        for (int r = 0; r < 4; r++)
            av[r] = *(const float4*)(aBase + r * AST + 4 * k4);
#pragma unroll
        for (int kk = 0; kk < 4; kk++) {
            int k = 4 * k4 + kk;
            ulonglong2 b01 = BsP[k * 32 + 2 * j];
            ulonglong2 b23 = BsP[k * 32 + 2 * j + 1];
#pragma unroll
            for (int r = 0; r < 4; r++) {
                unsigned long long ap = pack2(((const float*)&av[r])[kk]);
                FMA2(acc2[r][0], ap, b01.x);
                FMA2(acc2[r][1], ap, b01.y);
                FMA2(acc2[r][2], ap, b23.x);
                FMA2(acc2[r][3], ap, b23.y);
            }
        }
    }

    float4 bb0 = make_float4(0.f, 0.f, 0.f, 0.f), bb1 = bb0;
    if (bias) { bb0 = ((const float4*)bias)[2 * j]; bb1 = ((const float4*)bias)[2 * j + 1]; }

    float4 s0, s1, d0, d1;
    if (ATT) {
        s0 = __ldg(((const float4*)(att_src + l * 128)) + 2 * j);
        s1 = __ldg(((const float4*)(att_src + l * 128)) + 2 * j + 1);
        d0 = __ldg(((const float4*)(att_dst + l * 128)) + 2 * j);
        d1 = __ldg(((const float4*)(att_dst + l * 128)) + 2 * j + 1);
    }
    float ps[4], pd[4];

#pragma unroll
    for (int r = 0; r < 4; r++) {
        int grow = row0 + 4 * i + r;
        float2 p0 = unpack2(acc2[r][0]);
        float2 p1 = unpack2(acc2[r][1]);
        float2 p2 = unpack2(acc2[r][2]);
        float2 p3 = unpack2(acc2[r][3]);
        float4 o0 = make_float4(p0.x + bb0.x, p0.y + bb0.y, p1.x + bb0.z, p1.y + bb0.w);
        float4 o1 = make_float4(p2.x + bb1.x, p2.y + bb1.y, p3.x + bb1.z, p3.y + bb1.w);
        if (grow < M) {
            float4* cp = (float4*)(C + (size_t)grow * 128);
            cp[2 * j]     = o0;
            cp[2 * j + 1] = o1;
        }
        if (ATT) {
            ps[r] = o0.x * s0.x + o0.y * s0.y + o0.z * s0.z + o0.w * s0.w
                  + o1.x * s1.x + o1.y * s1.y + o1.z * s1.z + o1.w * s1.w;
            pd[r] = o0.x * d0.x + o0.y * d0.y + o0.z * d0.z + o0.w * d0.w
                  + o1.x * d1.x + o1.y * d1.y + o1.z * d1.z + o1.w * d1.w;
        }
    }

    if (ATT) {
        // reduce within 4-lane groups (lanes share head hh = j>>2)
#pragma unroll
        for (int r = 0; r < 4; r++) {
#pragma unroll
            for (int o = 1; o < 4; o <<= 1) {
                ps[r] += __shfl_xor_sync(0xffffffffu, ps[r], o);
                pd[r] += __shfl_xor_sync(0xffffffffu, pd[r], o);
            }
        }
        if ((j & 3) == 0) {
            const int hh = j >> 2;
            const float* Mh = g_M + l * 64 + hh;
            const float ch = g_c[l * 4 + hh];
#pragma unroll
            for (int r = 0; r < 4; r++) {
                int grow = row0 + 4 * i + r;
                if (grow >= M) continue;
                float ael = 0.f;
                float degv = (float)__ldg(g_degi + grow);
                if (degv > 0.f) {
                    const float* es = g_easum + grow * 16;
                    float sacc = 0.f;
#pragma unroll
                    for (int k = 0; k < 16; k++) sacc += es[k] * Mh[k * 4];
                    ael = sacc / degv + ch;
                }
                g_asrc[grow * 4 + hh] = ps[r];
                g_adst[grow * 4 + hh] = pd[r];
                g_aself[grow * 4 + hh] = lrelu(ps[r] + pd[r] + ael);
            }
        }
    }
}

// ---------------- fused GAT: softmax + aggregate + BN partial sums ----------------
__global__ __launch_bounds__(256) void gat_kernel(const float* __restrict__ bias_conv,
                                                  int l, int N) {
    __shared__ float4 swq[8][64];    // per-warp exp'd weights
    __shared__ int    sid[8][64];    // per-warp neighbor indices
    __shared__ float  sred[8][128];

    const int lane = threadIdx.x & 31;
    const int wl = threadIdx.x >> 5;               // 0..7
    const int warpsTotal = (gridDim.x * blockDim.x) >> 5;
    const int h = lane >> 3;
    const float4* aeB = (const float4*)g_ae[l];
    const float4 bq = __ldg(((const float4*)(bias_conv + l * 128)) + lane);

    float bs1[4] = {0.f, 0.f, 0.f, 0.f};
    float bs2[4] = {0.f, 0.f, 0.f, 0.f};

    for (int d = (blockIdx.x * blockDim.x + threadIdx.x) >> 5; d < N; d += warpsTotal) {
        const int start = __ldg(g_rowptr + d);
        const int deg = __ldg(g_degi + d);
        float4 ad = __ldg(((const float4*)g_adst) + d);
        float4 asf = __ldg(((const float4*)g_aself) + d);
        float4 m = asf;   // self-loop seeds the max
        float wsh, rdh;

        if (deg <= 64) {
            // ---- fast path: logits in registers, weights+indices in smem ----
            const bool v0 = lane < deg, v1 = lane + 32 < deg;
            float4 a0, a1;
            if (v0) {
                int s = __ldg(g_csrc + start + lane);
                sid[wl][lane] = s;
                float4 as = __ldg(((const float4*)g_asrc) + s);
                float4 ae = __ldg(aeB + start + lane);
                a0.x = lrelu(as.x + ad.x + ae.x); a0.y = lrelu(as.y + ad.y + ae.y);
                a0.z = lrelu(as.z + ad.z + ae.z); a0.w = lrelu(as.w + ad.w + ae.w);
                m = fmax4(m, a0);
            }
            if (v1) {
                int s = __ldg(g_csrc + start + lane + 32);
                sid[wl][lane + 32] = s;
                float4 as = __ldg(((const float4*)g_asrc) + s);
                float4 ae = __ldg(aeB + start + lane + 32);
                a1.x = lrelu(as.x + ad.x + ae.x); a1.y = lrelu(as.y + ad.y + ae.y);
                a1.z = lrelu(as.z + ad.z + ae.z); a1.w = lrelu(as.w + ad.w + ae.w);
                m = fmax4(m, a1);
            }
#pragma unroll
            for (int o = 16; o; o >>= 1) {
                m.x = fmaxf(m.x, __shfl_xor_sync(0xffffffffu, m.x, o));
                m.y = fmaxf(m.y, __shfl_xor_sync(0xffffffffu, m.y, o));
                m.z = fmaxf(m.z, __shfl_xor_sync(0xffffffffu, m.z, o));
                m.w = fmaxf(m.w, __shfl_xor_sync(0xffffffffu, m.w, o));
            }
            float4 den = make_float4(0.f, 0.f, 0.f, 0.f);
            if (v0) {
                float4 e;
                e.x = __expf(a0.x - m.x); e.y = __expf(a0.y - m.y);
                e.z = __expf(a0.z - m.z); e.w = __expf(a0.w - m.w);
                swq[wl][lane] = e;
                den.x += e.x; den.y += e.y; den.z += e.z; den.w += e.w;
            }
            if (v1) {
                float4 e;
                e.x = __expf(a1.x - m.x); e.y = __expf(a1.y - m.y);
                e.z = __expf(a1.z - m.z); e.w = __expf(a1.w - m.w);
                swq[wl][lane + 32] = e;
                den.x += e.x; den.y += e.y; den.z += e.z; den.w += e.w;
            }
#pragma unroll
            for (int o = 16; o; o >>= 1) {
                den.x += __shfl_xor_sync(0xffffffffu, den.x, o);
                den.y += __shfl_xor_sync(0xffffffffu, den.y, o);
                den.z += __shfl_xor_sync(0xffffffffu, den.z, o);
                den.w += __shfl_xor_sync(0xffffffffu, den.w, o);
            }
            __syncwarp();

            float asfh = sel4(asf, h), mh = sel4(m, h), denh = sel4(den, h);
            wsh = __expf(asfh - mh);
            rdh = 1.f / (denh + wsh + 1e-16f);

            float4 acc = __ldg(((const float4*)g_xh) + (size_t)d * 32 + lane);
            acc.x *= wsh; acc.y *= wsh; acc.z *= wsh; acc.w *= wsh;

            int jj = 0;
            for (; jj + 4 <= deg; jj += 4) {
#pragma unroll
                for (int q = 0; q < 4; q++) {
                    int s = sid[wl][jj + q];
                    float w = sel4(swq[wl][jj + q], h);
                    float4 v = __ldg(((const float4*)g_xh) + (size_t)s * 32 + lane);
                    acc.x += w * v.x; acc.y += w * v.y;
                    acc.z += w * v.z; acc.w += w * v.w;
                }
            }
            for (; jj < deg; jj++) {
                int s = sid[wl][jj];
                float w = sel4(swq[wl][jj], h);
                float4 v = __ldg(((const float4*)g_xh) + (size_t)s * 32 + lane);
                acc.x += w * v.x; acc.y += w * v.y;
                acc.z += w * v.z; acc.w += w * v.w;
            }
            float4 g;
            g.x = acc.x * rdh + bq.x; g.y = acc.y * rdh + bq.y;
            g.z = acc.z * rdh + bq.z; g.w = acc.w * rdh + bq.w;
            ((float4*)g_acc)[(size_t)d * 32 + lane] = g;
            bs1[0] += g.x; bs1[1] += g.y; bs1[2] += g.z; bs1[3] += g.w;
            bs2[0] += g.x * g.x; bs2[1] += g.y * g.y;
            bs2[2] += g.z * g.z; bs2[3] += g.w * g.w;
        } else {
            // ---- fallback: weights staged in global g_w ----
            for (int jj = lane; jj < deg; jj += 32) {
                int s = __ldg(g_csrc + start + jj);
                float4 as = __ldg(((const float4*)g_asrc) + s);
                float4 ae = __ldg(aeB + start + jj);
                float4 a;
                a.x = lrelu(as.x + ad.x + ae.x); a.y = lrelu(as.y + ad.y + ae.y);
                a.z = lrelu(as.z + ad.z + ae.z); a.w = lrelu(as.w + ad.w + ae.w);
                ((float4*)g_w)[start + jj] = a;
                m = fmax4(m, a);
            }
#pragma unroll
            for (int o = 16; o; o >>= 1) {
                m.x = fmaxf(m.x, __shfl_xor_sync(0xffffffffu, m.x, o));
                m.y = fmaxf(m.y, __shfl_xor_sync(0xffffffffu, m.y, o));
                m.z = fmaxf(m.z, __shfl_xor_sync(0xffffffffu, m.z, o));
                m.w = fmaxf(m.w, __shfl_xor_sync(0xffffffffu, m.w, o));
            }
            float4 den = make_float4(0.f, 0.f, 0.f, 0.f);
            for (int jj = lane; jj < deg; jj += 32) {
                float4 a = ((const float4*)g_w)[start + jj];
                a.x = __expf(a.x - m.x); a.y = __expf(a.y - m.y);
                a.z = __expf(a.z - m.z); a.w = __expf(a.w - m.w);
                ((float4*)g_w)[start + jj] = a;
                den.x += a.x; den.y += a.y; den.z += a.z; den.w += a.w;
            }
#pragma unroll
            for (int o = 16; o; o >>= 1) {
                den.x += __shfl_xor_sync(0xffffffffu, den.x, o);
                den.y += __shfl_xor_sync(0xffffffffu, den.y, o);
                den.z += __shfl_xor_sync(0xffffffffu, den.z, o);
                den.w += __shfl_xor_sync(0xffffffffu, den.w, o);
            }
            __syncwarp();
            float asfh = sel4(asf, h), mh = sel4(m, h), denh = sel4(den, h);
            wsh = __expf(asfh - mh);
            rdh = 1.f / (denh + wsh + 1e-16f);

            float4 acc = __ldg(((const float4*)g_xh) + (size_t)d * 32 + lane);
            acc.x *= wsh; acc.y *= wsh; acc.z *= wsh; acc.w *= wsh;
            for (int jj = 0; jj < deg; jj++) {
                float w = __ldg(g_w + (size_t)(start + jj) * 4 + h);
                int s = __ldg(g_csrc + start + jj);
                float4 v = __ldg(((const float4*)g_xh) + (size_t)s * 32 + lane);
                acc.x += w * v.x; acc.y += w * v.y;
                acc.z += w * v.z; acc.w += w * v.w;
            }
            float4 g;
            g.x = acc.x * rdh + bq.x; g.y = acc.y * rdh + bq.y;
            g.z = acc.z * rdh + bq.z; g.w = acc.w * rdh + bq.w;
            ((float4*)g_acc)[(size_t)d * 32 + lane] = g;
            bs1[0] += g.x; bs1[1] += g.y; bs1[2] += g.z; bs1[3] += g.w;
            bs2[0] += g.x * g.x; bs2[1] += g.y * g.y;
            bs2[2] += g.z * g.z; bs2[3] += g.w * g.w;
        }
    }

    // block-level BN reduction (8 warps x 128 channels)
#pragma unroll
    for (int q = 0; q < 4; q++) sred[wl][4 * lane + q] = bs1[q];
    __syncthreads();
    if (threadIdx.x < 128) {
        float s = 0.f;
#pragma unroll
        for (int w = 0; w < 8; w++) s += sred[w][threadIdx.x];
        atomicAdd(&g_bnsum[threadIdx.x], (double)s);
    }
    __syncthreads();
#pragma unroll
    for (int q = 0; q < 4; q++) sred[wl][4 * lane + q] = bs2[q];
    __syncthreads();
    if (threadIdx.x < 128) {
        float s = 0.f;
#pragma unroll
        for (int w = 0; w < 8; w++) s += sred[w][threadIdx.x];
        atomicAdd(&g_bnsq[threadIdx.x], (double)s);
    }
}

// ---------------- BN stats -> scale/shift (+ reset sums for next layer) ----------------
__global__ void bnstats_kernel(const float* __restrict__ gamma,
                               const float* __restrict__ beta, int l, int N) {
    int c = threadIdx.x;
    double mu = g_bnsum[c] / (double)N;
    double var = g_bnsq[c] / (double)N - mu * mu;
    float rstd = (float)rsqrt(var + 1e-5);
    float ga = gamma[l * 128 + c];
    g_bnscale[c] = ga * rstd;
    g_bnshift[c] = beta[l * 128 + c] - ga * (float)mu * rstd;
    g_bnsum[c] = 0.0;
    g_bnsq[c] = 0.0;
}

// ---------------- launcher ----------------
extern "C" void kernel_launch(void* const* d_in, const int* in_sizes, int n_in,
                              void* d_out, int out_size) {
    (void)n_in; (void)out_size;
    const float* x         = (const float*)d_in[0];
    const int*   ei        = (const int*)  d_in[1];
    const float* edge_attr = (const float*)d_in[2];
    const float* W_atom    = (const float*)d_in[3];
    const float* b_atom    = (const float*)d_in[4];
    const float* W_bond    = (const float*)d_in[5];
    const float* b_bond    = (const float*)d_in[6];
    const float* W_lin     = (const float*)d_in[7];
    const float* W_edge    = (const float*)d_in[8];
    const float* att_src   = (const float*)d_in[9];
    const float* att_dst   = (const float*)d_in[10];
    const float* att_edge  = (const float*)d_in[11];
    const float* bias_conv = (const float*)d_in[12];
    const float* bn_gamma  = (const float*)d_in[13];
    const float* bn_beta   = (const float*)d_in[14];
    const float* W_out     = (const float*)d_in[15];
    const float* b_out     = (const float*)d_in[16];
    float* out = (float*)d_out;

    const int N = in_sizes[0] / 64;
    const int E = in_sizes[1] / 2;
    const int nb = (N + SCAN_BLK - 1) / SCAN_BLK;

    const int smem128 = (128 * 128 + 64 * 132) * 4;
    const int smem64  = (64 * 128 + 64 * 68) * 4;
    cudaFuncSetAttribute(gemm_kernel<128, false, true>,  cudaFuncAttributeMaxDynamicSharedMemorySize, smem128);
    cudaFuncSetAttribute(gemm_kernel<128, true,  true>,  cudaFuncAttributeMaxDynamicSharedMemorySize, smem128);
    cudaFuncSetAttribute(gemm_kernel<128, true,  false>, cudaFuncAttributeMaxDynamicSharedMemorySize, smem128);
    cudaFuncSetAttribute(gemm_kernel<64,  false, false>, cudaFuncAttributeMaxDynamicSharedMemorySize, smem64);

    float* ph;   cudaGetSymbolAddress((void**)&ph,   g_h);
    float* pxh;  cudaGetSymbolAddress((void**)&pxh,  g_xh);
    float* pacc; cudaGetSymbolAddress((void**)&pacc, g_acc);

    // ---- preprocessing: deg/easum, folded consts, CSR counting sort ----
    prep_zero_kernel<<<(N * 16 + 255) / 256, 256>>>(N);
    consts_kernel<<<1, 128>>>(W_edge, att_edge, W_bond, b_bond);
    edge_prep_kernel<<<(E + 255) / 256, 256>>>(ei, edge_attr, E);
    scan_sum_kernel<<<nb, SCAN_BLK>>>(N);
    scan_mid_kernel<<<1, 32>>>(nb);
    scan_final_kernel<<<nb, SCAN_BLK>>>(N);
    scatter_kernel<<<(E + 255) / 256, 256>>>(ei, edge_attr, E);

    // ---- atom embedding ----
    gemm_kernel<64, false, false><<<(N + 63) / 64, 256, smem64>>>(
        x, W_atom, b_atom, ph, nullptr, nullptr, nullptr, 0, N);

    for (int l = 0; l < 3; l++) {
        if (l == 0)
            gemm_kernel<128, false, true><<<(N + 63) / 64, 256, smem128>>>(
                ph, W_lin, nullptr, pxh, nullptr, att_src, att_dst, 0, N);
        else
            gemm_kernel<128, true, true><<<(N + 63) / 64, 256, smem128>>>(
                pacc, W_lin + l * 128 * 128, nullptr, pxh, ph, att_src, att_dst, l, N);
        gat_kernel<<<1184, 256>>>(bias_conv, l, N);
        bnstats_kernel<<<1, 128>>>(bn_gamma, bn_beta, l, N);
    }

    // output projection with fused BN+ReLU+residual of layer 3
    gemm_kernel<128, true, false><<<(N + 63) / 64, 256, smem128>>>(
        pacc, W_out, b_out, out, ph, nullptr, nullptr, 0, N);
}

// round 12
// speedup vs baseline: 1.5818x; 1.0746x over previous
#include <cuda_runtime.h>
#include <math.h>

// ---------------- problem constants ----------------
#define HIDC 128
#define NMAX 50000
#define EMAX 600000
#define SCAN_BLK 512

// ---------------- device scratch ----------------
__device__ __align__(128) float g_h    [NMAX * HIDC];
__device__ __align__(128) float g_xh   [NMAX * HIDC];
__device__ __align__(128) float g_acc  [NMAX * HIDC];
__device__ __align__(128) float g_asrc [NMAX * 4];
__device__ __align__(128) float g_adst [NMAX * 4];
__device__ __align__(128) float g_M    [3 * 64];
__device__ __align__(128) float g_c    [3 * 4];
__device__ int   g_degi  [NMAX];
__device__ int   g_fill  [NMAX];
__device__ int   g_rowptr[NMAX];
__device__ int   g_bsum  [256];
__device__ __align__(128) int   g_csrc[EMAX];
__device__ __align__(128) float g_ae  [3][EMAX * 4];   // folded edge logits, CSR order
__device__ __align__(128) float g_w   [EMAX * 4];      // fallback scratch (deg>64 only)
__device__ double g_bnsum[HIDC];
__device__ double g_bnsq [HIDC];
__device__ __align__(128) float g_bnscale[HIDC];
__device__ __align__(128) float g_bnshift[HIDC];
__device__ unsigned int g_ctr = 0;

// ---------------- helpers ----------------
__device__ __forceinline__ float lrelu(float a) { return a > 0.f ? a : 0.2f * a; }

__device__ __forceinline__ unsigned long long pack2(float a) {
    unsigned long long r;
    asm("mov.b64 %0, {%1, %1};" : "=l"(r) : "r"(__float_as_uint(a)));
    return r;
}
__device__ __forceinline__ float2 unpack2(unsigned long long v) {
    unsigned int lo, hi;
    asm("mov.b64 {%0, %1}, %2;" : "=r"(lo), "=r"(hi) : "l"(v));
    return make_float2(__uint_as_float(lo), __uint_as_float(hi));
}
#define FMA2(acc, a2, b2) \
    asm("fma.rn.f32x2 %0, %1, %2, %0;" : "+l"(acc) : "l"(a2), "l"(b2))

__device__ __forceinline__ float sel4(float4 v, int h) {
    float ab = (h & 1) ? v.y : v.x;
    float cd = (h & 1) ? v.w : v.z;
    return (h & 2) ? cd : ab;
}
__device__ __forceinline__ float4 fmax4(float4 a, float4 b) {
    return make_float4(fmaxf(a.x, b.x), fmaxf(a.y, b.y), fmaxf(a.z, b.z), fmaxf(a.w, b.w));
}

// ---------------- prep: zeros ----------------
__global__ void prep_zero_kernel(int N) {
    int i = blockIdx.x * blockDim.x + threadIdx.x;
    if (i < N) { g_degi[i] = 0; g_fill[i] = 0; }
    if (i < 128) { g_bnsum[i] = 0.0; g_bnsq[i] = 0.0; }
}

// ---------------- per-layer folded constants (one block per layer) ----------------
__global__ void consts_kernel(const float* __restrict__ W_edge,
                              const float* __restrict__ att_edge,
                              const float* __restrict__ W_bond,
                              const float* __restrict__ b_bond) {
    __shared__ float Ve[128 * 4];
    int t = threadIdx.x; // 128 threads
    int l = blockIdx.x;  // 3 blocks
    const float* We = W_edge + l * 128 * 128 + t * 128;
    const float* ae = att_edge + l * 128;
    float v0 = 0.f, v1 = 0.f, v2 = 0.f, v3 = 0.f;
    for (int d = 0; d < 32; d++) {
        v0 += We[d]      * ae[d];
        v1 += We[32 + d] * ae[32 + d];
        v2 += We[64 + d] * ae[64 + d];
        v3 += We[96 + d] * ae[96 + d];
    }
    Ve[t * 4 + 0] = v0; Ve[t * 4 + 1] = v1; Ve[t * 4 + 2] = v2; Ve[t * 4 + 3] = v3;
    __syncthreads();
    if (t < 16) {
        float m0 = 0.f, m1 = 0.f, m2 = 0.f, m3 = 0.f;
        for (int k = 0; k < 128; k++) {
            float w = W_bond[t * 128 + k];
            m0 += w * Ve[k * 4 + 0]; m1 += w * Ve[k * 4 + 1];
            m2 += w * Ve[k * 4 + 2]; m3 += w * Ve[k * 4 + 3];
        }
        g_M[l * 64 + t * 4 + 0] = m0; g_M[l * 64 + t * 4 + 1] = m1;
        g_M[l * 64 + t * 4 + 2] = m2; g_M[l * 64 + t * 4 + 3] = m3;
    } else if (t < 20) {
        int h = t - 16;
        float cc = 0.f;
        for (int k = 0; k < 128; k++) cc += b_bond[k] * Ve[k * 4 + h];
        g_c[l * 4 + h] = cc;
    }
}

// ---------------- degree histogram only ----------------
__global__ void edge_prep_kernel(const int* __restrict__ ei, int E) {
    int e = blockIdx.x * blockDim.x + threadIdx.x;
    if (e < E) atomicAdd(&g_degi[ei[E + e]], 1);
}

// ---------------- exclusive scan of degi -> rowptr ----------------
__global__ void scan_sum_kernel(int N) {
    __shared__ int sh[16];
    int b = blockIdx.x, t = threadIdx.x;
    int i = b * SCAN_BLK + t;
    int v = (i < N) ? g_degi[i] : 0;
#pragma unroll
    for (int o = 16; o; o >>= 1) v += __shfl_xor_sync(0xffffffffu, v, o);
    if ((t & 31) == 0) sh[t >> 5] = v;
    __syncthreads();
    if (t < 16) {
        int s = sh[t];
#pragma unroll
        for (int o = 8; o; o >>= 1) s += __shfl_xor_sync(0xffffu, s, o);
        if (t == 0) g_bsum[b] = s;
    }
}
// block-parallel exclusive scan of g_bsum (nb <= 128)
__global__ void scan_mid_kernel(int nb) {
    __shared__ int ws[4];
    int t = threadIdx.x;   // 128 threads
    int lane = t & 31, w = t >> 5;
    int v = (t < nb) ? g_bsum[t] : 0;
    int x = v;
#pragma unroll
    for (int o = 1; o < 32; o <<= 1) {
        int y = __shfl_up_sync(0xffffffffu, x, o);
        if (lane >= o) x += y;
    }
    if (lane == 31) ws[w] = x;
    __syncthreads();
    if (t == 0) {
        int acc = 0;
#pragma unroll
        for (int q = 0; q < 4; q++) { int s = ws[q]; ws[q] = acc; acc += s; }
    }
    __syncthreads();
    if (t < nb) g_bsum[t] = x - v + ws[w];
}
__global__ void scan_final_kernel(int N) {
    __shared__ int wsum[16];
    int b = blockIdx.x, t = threadIdx.x;
    int i = b * SCAN_BLK + t;
    int v = (i < N) ? g_degi[i] : 0;
    int x = v;
#pragma unroll
    for (int o = 1; o < 32; o <<= 1) {
        int y = __shfl_up_sync(0xffffffffu, x, o);
        if ((t & 31) >= o) x += y;
    }
    if ((t & 31) == 31) wsum[t >> 5] = x;
    __syncthreads();
    if (t == 0) {
        int acc = 0;
        for (int w = 0; w < 16; w++) { int s = wsum[w]; wsum[w] = acc; acc += s; }
    }
    __syncthreads();
    if (i < N) g_rowptr[i] = x - v + wsum[t >> 5] + g_bsum[b];
}

// ---------------- counting-sort scatter: csr_src + folded edge logits per layer ----------------
__global__ void scatter_kernel(const int* __restrict__ ei,
                               const float* __restrict__ edge_attr, int E) {
    __shared__ float Ms[192];
    __shared__ float Cs[12];
    int t = threadIdx.x;
    if (t < 192) Ms[t] = g_M[t];
    if (t < 12)  Cs[t] = g_c[t];
    __syncthreads();
    int e = blockIdx.x * blockDim.x + t;
    if (e >= E) return;
    int s = ei[e], d = ei[E + e];
    int pos = g_rowptr[d] + atomicAdd(&g_fill[d], 1);
    g_csrc[pos] = s;
    float ev[16];
    const float4* ep = ((const float4*)edge_attr) + e * 4;
#pragma unroll
    for (int q = 0; q < 4; q++) {
        float4 v = ep[q];
        ev[4 * q] = v.x; ev[4 * q + 1] = v.y; ev[4 * q + 2] = v.z; ev[4 * q + 3] = v.w;
    }
#pragma unroll
    for (int l = 0; l < 3; l++) {
        float a0 = Cs[l * 4 + 0], a1 = Cs[l * 4 + 1], a2 = Cs[l * 4 + 2], a3 = Cs[l * 4 + 3];
#pragma unroll
        for (int k = 0; k < 16; k++) {
            float v = ev[k];
            a0 += v * Ms[l * 64 + k * 4 + 0]; a1 += v * Ms[l * 64 + k * 4 + 1];
            a2 += v * Ms[l * 64 + k * 4 + 2]; a3 += v * Ms[l * 64 + k * 4 + 3];
        }
        ((float4*)g_ae[l])[pos] = make_float4(a0, a1, a2, a3);
    }
}

// ---------------- GEMM: C[M,128] = A'[M,K] @ B[K,128] (+ bias) ----------------
// FUSEBN: A' = relu(A*bnscale + bnshift) + hres, new h written back to hres.
// ATT:    epilogue also computes a_src/a_dst per (node, head) from C.
template <int K, bool FUSEBN, bool ATT>
__global__ __launch_bounds__(256) void gemm_kernel(const float* __restrict__ A,
                                                   const float* __restrict__ B,
                                                   const float* __restrict__ bias,
                                                   float* __restrict__ C,
                                                   float* __restrict__ hres,
                                                   const float* __restrict__ att_src,
                                                   const float* __restrict__ att_dst,
                                                   int l, int M) {
    constexpr int AST = K + 4;  // padded row stride (floats), 16B-aligned
    extern __shared__ float sm[];
    float* Bs = sm;               // K*128
    float* As = sm + K * 128;     // 64*AST
    const int t = threadIdx.x;
    const int row0 = blockIdx.x * 64;

    for (int idx = t; idx < K * 32; idx += 256)
        ((float4*)Bs)[idx] = ((const float4*)B)[idx];

    constexpr int KQ = K / 4;
    for (int idx = t; idx < 64 * KQ; idx += 256) {
        int r = idx / KQ, q = idx - r * KQ;
        int grow = row0 + r;
        float4 o = make_float4(0.f, 0.f, 0.f, 0.f);
        if (grow < M) {
            float4 v = ((const float4*)(A + (size_t)grow * K))[q];
            if (FUSEBN) {
                float4 hv = ((const float4*)(hres + (size_t)grow * K))[q];
                float4 sc = __ldg(((const float4*)g_bnscale) + q);
                float4 sh = __ldg(((const float4*)g_bnshift) + q);
                o.x = fmaxf(fmaf(v.x, sc.x, sh.x), 0.f) + hv.x;
                o.y = fmaxf(fmaf(v.y, sc.y, sh.y), 0.f) + hv.y;
                o.z = fmaxf(fmaf(v.z, sc.z, sh.z), 0.f) + hv.z;
                o.w = fmaxf(fmaf(v.w, sc.w, sh.w), 0.f) + hv.w;
                ((float4*)(hres + (size_t)grow * K))[q] = o;
            } else {
                o = v;
            }
        }
        *(float4*)(As + r * AST + 4 * q) = o;
    }
    __syncthreads();

    const int j = t & 15;   // cols 8j..8j+7
    const int i = t >> 4;   // rows 4i..4i+3
    unsigned long long acc2[4][4] = {};   // 4 rows x 4 packed col-pairs

    const float* aBase = As + (4 * i) * AST;
    const ulonglong2* BsP = (const ulonglong2*)Bs;   // 32 ulonglong2 per row
#pragma unroll 2
    for (int k4 = 0; k4 < K / 4; k4++) {
        float4 av[4];
#pragma unroll
        for (int r = 0; r < 4; r++)
            av[r] = *(const float4*)(aBase + r * AST + 4 * k4);
#pragma unroll
        for (int kk = 0; kk < 4; kk++) {
            int k = 4 * k4 + kk;
            ulonglong2 b01 = BsP[k * 32 + 2 * j];
            ulonglong2 b23 = BsP[k * 32 + 2 * j + 1];
#pragma unroll
            for (int r = 0; r < 4; r++) {
                unsigned long long ap = pack2(((const float*)&av[r])[kk]);
                FMA2(acc2[r][0], ap, b01.x);
                FMA2(acc2[r][1], ap, b01.y);
                FMA2(acc2[r][2], ap, b23.x);
                FMA2(acc2[r][3], ap, b23.y);
            }
        }
    }

    float4 bb0 = make_float4(0.f, 0.f, 0.f, 0.f), bb1 = bb0;
    if (bias) { bb0 = ((const float4*)bias)[2 * j]; bb1 = ((const float4*)bias)[2 * j + 1]; }

    float4 s0, s1, d0, d1;
    if (ATT) {
        s0 = __ldg(((const float4*)(att_src + l * 128)) + 2 * j);
        s1 = __ldg(((const float4*)(att_src + l * 128)) + 2 * j + 1);
        d0 = __ldg(((const float4*)(att_dst + l * 128)) + 2 * j);
        d1 = __ldg(((const float4*)(att_dst + l * 128)) + 2 * j + 1);
    }
    float ps[4], pd[4];

#pragma unroll
    for (int r = 0; r < 4; r++) {
        int grow = row0 + 4 * i + r;
        float2 p0 = unpack2(acc2[r][0]);
        float2 p1 = unpack2(acc2[r][1]);
        float2 p2 = unpack2(acc2[r][2]);
        float2 p3 = unpack2(acc2[r][3]);
        float4 o0 = make_float4(p0.x + bb0.x, p0.y + bb0.y, p1.x + bb0.z, p1.y + bb0.w);
        float4 o1 = make_float4(p2.x + bb1.x, p2.y + bb1.y, p3.x + bb1.z, p3.y + bb1.w);
        if (grow < M) {
            float4* cp = (float4*)(C + (size_t)grow * 128);
            cp[2 * j]     = o0;
            cp[2 * j + 1] = o1;
        }
        if (ATT) {
            ps[r] = o0.x * s0.x + o0.y * s0.y + o0.z * s0.z + o0.w * s0.w
                  + o1.x * s1.x + o1.y * s1.y + o1.z * s1.z + o1.w * s1.w;
            pd[r] = o0.x * d0.x + o0.y * d0.y + o0.z * d0.z + o0.w * d0.w
                  + o1.x * d1.x + o1.y * d1.y + o1.z * d1.z + o1.w * d1.w;
        }
    }

    if (ATT) {
#pragma unroll
        for (int r = 0; r < 4; r++) {
#pragma unroll
            for (int o = 1; o < 4; o <<= 1) {
                ps[r] += __shfl_xor_sync(0xffffffffu, ps[r], o);
                pd[r] += __shfl_xor_sync(0xffffffffu, pd[r], o);
            }
        }
        if ((j & 3) == 0) {
            const int hh = j >> 2;
#pragma unroll
            for (int r = 0; r < 4; r++) {
                int grow = row0 + 4 * i + r;
                if (grow >= M) continue;
                g_asrc[grow * 4 + hh] = ps[r];
                g_adst[grow * 4 + hh] = pd[r];
            }
        }
    }
}

// ---------------- fused GAT: softmax + aggregate + BN stats (w/ fused bnstats tail) ----------------
__global__ __launch_bounds__(256) void gat_kernel(const float* __restrict__ bias_conv,
                                                  const float* __restrict__ gamma,
                                                  const float* __restrict__ beta,
                                                  int l, int N) {
    __shared__ float4 swq[8][64];    // per-warp exp'd weights
    __shared__ int    sid[8][64];    // per-warp neighbor indices
    __shared__ float  sred[8][128];

    const int lane = threadIdx.x & 31;
    const int wl = threadIdx.x >> 5;               // 0..7
    const int warpsTotal = (gridDim.x * blockDim.x) >> 5;
    const int h = lane >> 3;
    const float4* aeB = (const float4*)g_ae[l];
    const float4 bq = __ldg(((const float4*)(bias_conv + l * 128)) + lane);
    const float NEG = -3.0e38f;

    float bs1[4] = {0.f, 0.f, 0.f, 0.f};
    float bs2[4] = {0.f, 0.f, 0.f, 0.f};

    for (int d = (blockIdx.x * blockDim.x + threadIdx.x) >> 5; d < N; d += warpsTotal) {
        const int start = __ldg(g_rowptr + d);
        const int deg = __ldg(g_degi + d);
        float4 ad  = __ldg(((const float4*)g_adst) + d);
        float4 asd = __ldg(((const float4*)g_asrc) + d);
        float4 m = make_float4(NEG, NEG, NEG, NEG);
        float4 aes = make_float4(0.f, 0.f, 0.f, 0.f);

        if (deg <= 64) {
            // ---- fast path: logits in registers, weights+indices in smem ----
            const bool v0 = lane < deg, v1 = lane + 32 < deg;
            float4 a0, a1;
            if (v0) {
                int s = __ldg(g_csrc + start + lane);
                sid[wl][lane] = s;
                float4 as = __ldg(((const float4*)g_asrc) + s);
                float4 ae = __ldg(aeB + start + lane);
                aes.x += ae.x; aes.y += ae.y; aes.z += ae.z; aes.w += ae.w;
                a0.x = lrelu(as.x + ad.x + ae.x); a0.y = lrelu(as.y + ad.y + ae.y);
                a0.z = lrelu(as.z + ad.z + ae.z); a0.w = lrelu(as.w + ad.w + ae.w);
                m = fmax4(m, a0);
            }
            if (v1) {
                int s = __ldg(g_csrc + start + lane + 32);
                sid[wl][lane + 32] = s;
                float4 as = __ldg(((const float4*)g_asrc) + s);
                float4 ae = __ldg(aeB + start + lane + 32);
                aes.x += ae.x; aes.y += ae.y; aes.z += ae.z; aes.w += ae.w;
                a1.x = lrelu(as.x + ad.x + ae.x); a1.y = lrelu(as.y + ad.y + ae.y);
                a1.z = lrelu(as.z + ad.z + ae.z); a1.w = lrelu(as.w + ad.w + ae.w);
                m = fmax4(m, a1);
            }
#pragma unroll
            for (int o = 16; o; o >>= 1) {
                m.x = fmaxf(m.x, __shfl_xor_sync(0xffffffffu, m.x, o));
                m.y = fmaxf(m.y, __shfl_xor_sync(0xffffffffu, m.y, o));
                m.z = fmaxf(m.z, __shfl_xor_sync(0xffffffffu, m.z, o));
                m.w = fmaxf(m.w, __shfl_xor_sync(0xffffffffu, m.w, o));
                aes.x += __shfl_xor_sync(0xffffffffu, aes.x, o);
                aes.y += __shfl_xor_sync(0xffffffffu, aes.y, o);
                aes.z += __shfl_xor_sync(0xffffffffu, aes.z, o);
                aes.w += __shfl_xor_sync(0xffffffffu, aes.w, o);
            }
            // self-loop logit: mean of folded edge logits (== ea_loop path)
            float4 asf;
            if (deg > 0) {
                float rdeg = 1.f / (float)deg;
                asf.x = lrelu(asd.x + ad.x + aes.x * rdeg);
                asf.y = lrelu(asd.y + ad.y + aes.y * rdeg);
                asf.z = lrelu(asd.z + ad.z + aes.z * rdeg);
                asf.w = lrelu(asd.w + ad.w + aes.w * rdeg);
            } else {
                asf.x = lrelu(asd.x + ad.x); asf.y = lrelu(asd.y + ad.y);
                asf.z = lrelu(asd.z + ad.z); asf.w = lrelu(asd.w + ad.w);
            }
            m = fmax4(m, asf);

            float4 den = make_float4(0.f, 0.f, 0.f, 0.f);
            if (v0) {
                float4 e;
                e.x = __expf(a0.x - m.x); e.y = __expf(a0.y - m.y);
                e.z = __expf(a0.z - m.z); e.w = __expf(a0.w - m.w);
                swq[wl][lane] = e;
                den.x += e.x; den.y += e.y; den.z += e.z; den.w += e.w;
            }
            if (v1) {
                float4 e;
                e.x = __expf(a1.x - m.x); e.y = __expf(a1.y - m.y);
                e.z = __expf(a1.z - m.z); e.w = __expf(a1.w - m.w);
                swq[wl][lane + 32] = e;
                den.x += e.x; den.y += e.y; den.z += e.z; den.w += e.w;
            }
#pragma unroll
            for (int o = 16; o; o >>= 1) {
                den.x += __shfl_xor_sync(0xffffffffu, den.x, o);
                den.y += __shfl_xor_sync(0xffffffffu, den.y, o);
                den.z += __shfl_xor_sync(0xffffffffu, den.z, o);
                den.w += __shfl_xor_sync(0xffffffffu, den.w, o);
            }
            __syncwarp();

            float asfh = sel4(asf, h), mh = sel4(m, h), denh = sel4(den, h);
            float wsh = __expf(asfh - mh);
            float rdh = 1.f / (denh + wsh + 1e-16f);

            float4 acc = __ldg(((const float4*)g_xh) + (size_t)d * 32 + lane);
            acc.x *= wsh; acc.y *= wsh; acc.z *= wsh; acc.w *= wsh;

            int jj = 0;
            for (; jj + 4 <= deg; jj += 4) {
#pragma unroll
                for (int q = 0; q < 4; q++) {
                    int s = sid[wl][jj + q];
                    float w = sel4(swq[wl][jj + q], h);
                    float4 v = __ldg(((const float4*)g_xh) + (size_t)s * 32 + lane);
                    acc.x += w * v.x; acc.y += w * v.y;
                    acc.z += w * v.z; acc.w += w * v.w;
                }
            }
            for (; jj < deg; jj++) {
                int s = sid[wl][jj];
                float w = sel4(swq[wl][jj], h);
                float4 v = __ldg(((const float4*)g_xh) + (size_t)s * 32 + lane);
                acc.x += w * v.x; acc.y += w * v.y;
                acc.z += w * v.z; acc.w += w * v.w;
            }
            float4 g;
            g.x = acc.x * rdh + bq.x; g.y = acc.y * rdh + bq.y;
            g.z = acc.z * rdh + bq.z; g.w = acc.w * rdh + bq.w;
            ((float4*)g_acc)[(size_t)d * 32 + lane] = g;
            bs1[0] += g.x; bs1[1] += g.y; bs1[2] += g.z; bs1[3] += g.w;
            bs2[0] += g.x * g.x; bs2[1] += g.y * g.y;
            bs2[2] += g.z * g.z; bs2[3] += g.w * g.w;
        } else {
            // ---- fallback: weights staged in global g_w ----
            for (int jj = lane; jj < deg; jj += 32) {
                int s = __ldg(g_csrc + start + jj);
                float4 as = __ldg(((const float4*)g_asrc) + s);
                float4 ae = __ldg(aeB + start + jj);
                aes.x += ae.x; aes.y += ae.y; aes.z += ae.z; aes.w += ae.w;
                float4 a;
                a.x = lrelu(as.x + ad.x + ae.x); a.y = lrelu(as.y + ad.y + ae.y);
                a.z = lrelu(as.z + ad.z + ae.z); a.w = lrelu(as.w + ad.w + ae.w);
                ((float4*)g_w)[start + jj] = a;
                m = fmax4(m, a);
            }
#pragma unroll
            for (int o = 16; o; o >>= 1) {
                m.x = fmaxf(m.x, __shfl_xor_sync(0xffffffffu, m.x, o));
                m.y = fmaxf(m.y, __shfl_xor_sync(0xffffffffu, m.y, o));
                m.z = fmaxf(m.z, __shfl_xor_sync(0xffffffffu, m.z, o));
                m.w = fmaxf(m.w, __shfl_xor_sync(0xffffffffu, m.w, o));
                aes.x += __shfl_xor_sync(0xffffffffu, aes.x, o);
                aes.y += __shfl_xor_sync(0xffffffffu, aes.y, o);
                aes.z += __shfl_xor_sync(0xffffffffu, aes.z, o);
                aes.w += __shfl_xor_sync(0xffffffffu, aes.w, o);
            }
            float rdeg = 1.f / (float)deg;
            float4 asf;
            asf.x = lrelu(asd.x + ad.x + aes.x * rdeg);
            asf.y = lrelu(asd.y + ad.y + aes.y * rdeg);
            asf.z = lrelu(asd.z + ad.z + aes.z * rdeg);
            asf.w = lrelu(asd.w + ad.w + aes.w * rdeg);
            m = fmax4(m, asf);

            float4 den = make_float4(0.f, 0.f, 0.f, 0.f);
            for (int jj = lane; jj < deg; jj += 32) {
                float4 a = ((const float4*)g_w)[start + jj];
                a.x = __expf(a.x - m.x); a.y = __expf(a.y - m.y);
                a.z = __expf(a.z - m.z); a.w = __expf(a.w - m.w);
                ((float4*)g_w)[start + jj] = a;
                den.x += a.x; den.y += a.y; den.z += a.z; den.w += a.w;
            }
#pragma unroll
            for (int o = 16; o; o >>= 1) {
                den.x += __shfl_xor_sync(0xffffffffu, den.x, o);
                den.y += __shfl_xor_sync(0xffffffffu, den.y, o);
                den.z += __shfl_xor_sync(0xffffffffu, den.z, o);
                den.w += __shfl_xor_sync(0xffffffffu, den.w, o);
            }
            __syncwarp();
            float asfh = sel4(asf, h), mh = sel4(m, h), denh = sel4(den, h);
            float wsh = __expf(asfh - mh);
            float rdh = 1.f / (denh + wsh + 1e-16f);

            float4 acc = __ldg(((const float4*)g_xh) + (size_t)d * 32 + lane);
            acc.x *= wsh; acc.y *= wsh; acc.z *= wsh; acc.w *= wsh;
            for (int jj = 0; jj < deg; jj++) {
                float w = __ldg(g_w + (size_t)(start + jj) * 4 + h);
                int s = __ldg(g_csrc + start + jj);
                float4 v = __ldg(((const float4*)g_xh) + (size_t)s * 32 + lane);
                acc.x += w * v.x; acc.y += w * v.y;
                acc.z += w * v.z; acc.w += w * v.w;
            }
            float4 g;
            g.x = acc.x * rdh + bq.x; g.y = acc.y * rdh + bq.y;
            g.z = acc.z * rdh + bq.z; g.w = acc.w * rdh + bq.w;
            ((float4*)g_acc)[(size_t)d * 32 + lane] = g;
            bs1[0] += g.x; bs1[1] += g.y; bs1[2] += g.z; bs1[3] += g.w;
            bs2[0] += g.x * g.x; bs2[1] += g.y * g.y;
            bs2[2] += g.z * g.z; bs2[3] += g.w * g.w;
        }
    }

    // block-level BN reduction (8 warps x 128 channels)
#pragma unroll
    for (int q = 0; q < 4; q++) sred[wl][4 * lane + q] = bs1[q];
    __syncthreads();
    if (threadIdx.x < 128) {
        float s = 0.f;
#pragma unroll
        for (int w = 0; w < 8; w++) s += sred[w][threadIdx.x];
        atomicAdd(&g_bnsum[threadIdx.x], (double)s);
    }
    __syncthreads();
#pragma unroll
    for (int q = 0; q < 4; q++) sred[wl][4 * lane + q] = bs2[q];
    __syncthreads();
    if (threadIdx.x < 128) {
        float s = 0.f;
#pragma unroll
        for (int w = 0; w < 8; w++) s += sred[w][threadIdx.x];
        atomicAdd(&g_bnsq[threadIdx.x], (double)s);
    }

    // ---- fused bnstats: last block computes scale/shift, resets sums/counter ----
    __shared__ bool isLast;
    __threadfence();
    if (threadIdx.x == 0)
        isLast = (atomicAdd(&g_ctr, 1u) == gridDim.x - 1u);
    __syncthreads();
    if (isLast) {
        if (threadIdx.x < 128) {
            int c = threadIdx.x;
            double mu = g_bnsum[c] / (double)N;
            double var = g_bnsq[c] / (double)N - mu * mu;
            float rstd = (float)rsqrt(var + 1e-5);
            float ga = gamma[l * 128 + c];
            g_bnscale[c] = ga * rstd;
            g_bnshift[c] = beta[l * 128 + c] - ga * (float)mu * rstd;
            g_bnsum[c] = 0.0;
            g_bnsq[c] = 0.0;
        }
        if (threadIdx.x == 0) g_ctr = 0;
    }
}

// ---------------- launcher ----------------
extern "C" void kernel_launch(void* const* d_in, const int* in_sizes, int n_in,
                              void* d_out, int out_size) {
    (void)n_in; (void)out_size;
    const float* x         = (const float*)d_in[0];
    const int*   ei        = (const int*)  d_in[1];
    const float* edge_attr = (const float*)d_in[2];
    const float* W_atom    = (const float*)d_in[3];
    const float* b_atom    = (const float*)d_in[4];
    const float* W_bond    = (const float*)d_in[5];
    const float* b_bond    = (const float*)d_in[6];
    const float* W_lin     = (const float*)d_in[7];
    const float* W_edge    = (const float*)d_in[8];
    const float* att_src   = (const float*)d_in[9];
    const float* att_dst   = (const float*)d_in[10];
    const float* att_edge  = (const float*)d_in[11];
    const float* bias_conv = (const float*)d_in[12];
    const float* bn_gamma  = (const float*)d_in[13];
    const float* bn_beta   = (const float*)d_in[14];
    const float* W_out     = (const float*)d_in[15];
    const float* b_out     = (const float*)d_in[16];
    float* out = (float*)d_out;

    const int N = in_sizes[0] / 64;
    const int E = in_sizes[1] / 2;
    const int nb = (N + SCAN_BLK - 1) / SCAN_BLK;

    const int smem128 = (128 * 128 + 64 * 132) * 4;
    const int smem64  = (64 * 128 + 64 * 68) * 4;
    cudaFuncSetAttribute(gemm_kernel<128, false, true>,  cudaFuncAttributeMaxDynamicSharedMemorySize, smem128);
    cudaFuncSetAttribute(gemm_kernel<128, true,  true>,  cudaFuncAttributeMaxDynamicSharedMemorySize, smem128);
    cudaFuncSetAttribute(gemm_kernel<128, true,  false>, cudaFuncAttributeMaxDynamicSharedMemorySize, smem128);
    cudaFuncSetAttribute(gemm_kernel<64,  false, false>, cudaFuncAttributeMaxDynamicSharedMemorySize, smem64);

    float* ph;   cudaGetSymbolAddress((void**)&ph,   g_h);
    float* pxh;  cudaGetSymbolAddress((void**)&pxh,  g_xh);
    float* pacc; cudaGetSymbolAddress((void**)&pacc, g_acc);

    // ---- preprocessing: deg, folded consts, CSR counting sort ----
    prep_zero_kernel<<<(N + 255) / 256, 256>>>(N);
    consts_kernel<<<3, 128>>>(W_edge, att_edge, W_bond, b_bond);
    edge_prep_kernel<<<(E + 255) / 256, 256>>>(ei, E);
    scan_sum_kernel<<<nb, SCAN_BLK>>>(N);
    scan_mid_kernel<<<1, 128>>>(nb);
    scan_final_kernel<<<nb, SCAN_BLK>>>(N);
    scatter_kernel<<<(E + 255) / 256, 256>>>(ei, edge_attr, E);

    // ---- atom embedding ----
    gemm_kernel<64, false, false><<<(N + 63) / 64, 256, smem64>>>(
        x, W_atom, b_atom, ph, nullptr, nullptr, nullptr, 0, N);

    for (int l = 0; l < 3; l++) {
        if (l == 0)
            gemm_kernel<128, false, true><<<(N + 63) / 64, 256, smem128>>>(
                ph, W_lin, nullptr, pxh, nullptr, att_src, att_dst, 0, N);
        else
            gemm_kernel<128, true, true><<<(N + 63) / 64, 256, smem128>>>(
                pacc, W_lin + l * 128 * 128, nullptr, pxh, ph, att_src, att_dst, l, N);
        gat_kernel<<<1184, 256>>>(bias_conv, bn_gamma, bn_beta, l, N);
    }

    // output projection with fused BN+ReLU+residual of layer 3
    gemm_kernel<128, true, false><<<(N + 63) / 64, 256, smem128>>>(
        pacc, W_out, b_out, out, ph, nullptr, nullptr, 0, N);
}

// round 13
// speedup vs baseline: 1.6062x; 1.0154x over previous
#include <cuda_runtime.h>
#include <math.h>

// ---------------- problem constants ----------------
#define HIDC 128
#define NMAX 50000
#define EMAX 600000
#define SCAN_BLK 512

// ---------------- device scratch ----------------
__device__ __align__(128) float g_h    [NMAX * HIDC];
__device__ __align__(128) float g_xh   [NMAX * HIDC];
__device__ __align__(128) float g_acc  [NMAX * HIDC];
__device__ __align__(128) float g_asrc [NMAX * 4];
__device__ __align__(128) float g_adst [NMAX * 4];
__device__ __align__(128) float g_M    [3 * 64];
__device__ __align__(128) float g_c    [3 * 4];
__device__ int   g_degi  [NMAX];
__device__ int   g_fill  [NMAX];
__device__ int   g_rowptr[NMAX];
__device__ int   g_bsum  [256];
__device__ __align__(128) int   g_csrc[EMAX];
__device__ __align__(128) float g_ae  [3][EMAX * 4];   // folded edge logits, CSR order
__device__ __align__(128) float g_w   [EMAX * 4];      // fallback scratch (deg>64 only)
__device__ double g_bnsum[HIDC];
__device__ double g_bnsq [HIDC];
__device__ __align__(128) float g_bnscale[HIDC];
__device__ __align__(128) float g_bnshift[HIDC];
__device__ unsigned int g_ctr = 0;

// ---------------- helpers ----------------
__device__ __forceinline__ float lrelu(float a) { return a > 0.f ? a : 0.2f * a; }

__device__ __forceinline__ unsigned long long pack2(float a) {
    unsigned long long r;
    asm("mov.b64 %0, {%1, %1};" : "=l"(r) : "r"(__float_as_uint(a)));
    return r;
}
__device__ __forceinline__ float2 unpack2(unsigned long long v) {
    unsigned int lo, hi;
    asm("mov.b64 {%0, %1}, %2;" : "=r"(lo), "=r"(hi) : "l"(v));
    return make_float2(__uint_as_float(lo), __uint_as_float(hi));
}
#define FMA2(acc, a2, b2) \
    asm("fma.rn.f32x2 %0, %1, %2, %0;" : "+l"(acc) : "l"(a2), "l"(b2))

__device__ __forceinline__ float sel4(float4 v, int h) {
    float ab = (h & 1) ? v.y : v.x;
    float cd = (h & 1) ? v.w : v.z;
    return (h & 2) ? cd : ab;
}
__device__ __forceinline__ float4 fmax4(float4 a, float4 b) {
    return make_float4(fmaxf(a.x, b.x), fmaxf(a.y, b.y), fmaxf(a.z, b.z), fmaxf(a.w, b.w));
}

// ---------------- prep: zeros ----------------
__global__ void prep_zero_kernel(int N) {
    int i = blockIdx.x * blockDim.x + threadIdx.x;
    if (i < N) { g_degi[i] = 0; g_fill[i] = 0; }
    if (i < 128) { g_bnsum[i] = 0.0; g_bnsq[i] = 0.0; }
}

// ---------------- per-layer folded constants (one block per layer) ----------------
__global__ void consts_kernel(const float* __restrict__ W_edge,
                              const float* __restrict__ att_edge,
                              const float* __restrict__ W_bond,
                              const float* __restrict__ b_bond) {
    __shared__ float Ve[128 * 4];
    int t = threadIdx.x; // 128 threads
    int l = blockIdx.x;  // 3 blocks
    const float* We = W_edge + l * 128 * 128 + t * 128;
    const float* ae = att_edge + l * 128;
    float v0 = 0.f, v1 = 0.f, v2 = 0.f, v3 = 0.f;
    for (int d = 0; d < 32; d++) {
        v0 += We[d]      * ae[d];
        v1 += We[32 + d] * ae[32 + d];
        v2 += We[64 + d] * ae[64 + d];
        v3 += We[96 + d] * ae[96 + d];
    }
    Ve[t * 4 + 0] = v0; Ve[t * 4 + 1] = v1; Ve[t * 4 + 2] = v2; Ve[t * 4 + 3] = v3;
    __syncthreads();
    if (t < 16) {
        float m0 = 0.f, m1 = 0.f, m2 = 0.f, m3 = 0.f;
        for (int k = 0; k < 128; k++) {
            float w = W_bond[t * 128 + k];
            m0 += w * Ve[k * 4 + 0]; m1 += w * Ve[k * 4 + 1];
            m2 += w * Ve[k * 4 + 2]; m3 += w * Ve[k * 4 + 3];
        }
        g_M[l * 64 + t * 4 + 0] = m0; g_M[l * 64 + t * 4 + 1] = m1;
        g_M[l * 64 + t * 4 + 2] = m2; g_M[l * 64 + t * 4 + 3] = m3;
    } else if (t < 20) {
        int h = t - 16;
        float cc = 0.f;
        for (int k = 0; k < 128; k++) cc += b_bond[k] * Ve[k * 4 + h];
        g_c[l * 4 + h] = cc;
    }
}

// ---------------- degree histogram only ----------------
__global__ void edge_prep_kernel(const int* __restrict__ ei, int E) {
    int e = blockIdx.x * blockDim.x + threadIdx.x;
    if (e < E) atomicAdd(&g_degi[ei[E + e]], 1);
}

// ---------------- exclusive scan of degi -> rowptr ----------------
__global__ void scan_sum_kernel(int N) {
    __shared__ int sh[16];
    int b = blockIdx.x, t = threadIdx.x;
    int i = b * SCAN_BLK + t;
    int v = (i < N) ? g_degi[i] : 0;
#pragma unroll
    for (int o = 16; o; o >>= 1) v += __shfl_xor_sync(0xffffffffu, v, o);
    if ((t & 31) == 0) sh[t >> 5] = v;
    __syncthreads();
    if (t < 16) {
        int s = sh[t];
#pragma unroll
        for (int o = 8; o; o >>= 1) s += __shfl_xor_sync(0xffffu, s, o);
        if (t == 0) g_bsum[b] = s;
    }
}
__global__ void scan_mid_kernel(int nb) {
    __shared__ int ws[4];
    int t = threadIdx.x;   // 128 threads
    int lane = t & 31, w = t >> 5;
    int v = (t < nb) ? g_bsum[t] : 0;
    int x = v;
#pragma unroll
    for (int o = 1; o < 32; o <<= 1) {
        int y = __shfl_up_sync(0xffffffffu, x, o);
        if (lane >= o) x += y;
    }
    if (lane == 31) ws[w] = x;
    __syncthreads();
    if (t == 0) {
        int acc = 0;
#pragma unroll
        for (int q = 0; q < 4; q++) { int s = ws[q]; ws[q] = acc; acc += s; }
    }
    __syncthreads();
    if (t < nb) g_bsum[t] = x - v + ws[w];
}
__global__ void scan_final_kernel(int N) {
    __shared__ int wsum[16];
    int b = blockIdx.x, t = threadIdx.x;
    int i = b * SCAN_BLK + t;
    int v = (i < N) ? g_degi[i] : 0;
    int x = v;
#pragma unroll
    for (int o = 1; o < 32; o <<= 1) {
        int y = __shfl_up_sync(0xffffffffu, x, o);
        if ((t & 31) >= o) x += y;
    }
    if ((t & 31) == 31) wsum[t >> 5] = x;
    __syncthreads();
    if (t == 0) {
        int acc = 0;
        for (int w = 0; w < 16; w++) { int s = wsum[w]; wsum[w] = acc; acc += s; }
    }
    __syncthreads();
    if (i < N) g_rowptr[i] = x - v + wsum[t >> 5] + g_bsum[b];
}

// ---------------- counting-sort scatter: csr_src + folded edge logits per layer ----------------
__global__ void scatter_kernel(const int* __restrict__ ei,
                               const float* __restrict__ edge_attr, int E) {
    __shared__ float Ms[192];
    __shared__ float Cs[12];
    int t = threadIdx.x;
    if (t < 192) Ms[t] = g_M[t];
    if (t < 12)  Cs[t] = g_c[t];
    __syncthreads();
    int e = blockIdx.x * blockDim.x + t;
    if (e >= E) return;
    int s = ei[e], d = ei[E + e];
    int pos = g_rowptr[d] + atomicAdd(&g_fill[d], 1);
    g_csrc[pos] = s;
    float ev[16];
    const float4* ep = ((const float4*)edge_attr) + e * 4;
#pragma unroll
    for (int q = 0; q < 4; q++) {
        float4 v = ep[q];
        ev[4 * q] = v.x; ev[4 * q + 1] = v.y; ev[4 * q + 2] = v.z; ev[4 * q + 3] = v.w;
    }
#pragma unroll
    for (int l = 0; l < 3; l++) {
        float a0 = Cs[l * 4 + 0], a1 = Cs[l * 4 + 1], a2 = Cs[l * 4 + 2], a3 = Cs[l * 4 + 3];
#pragma unroll
        for (int k = 0; k < 16; k++) {
            float v = ev[k];
            a0 += v * Ms[l * 64 + k * 4 + 0]; a1 += v * Ms[l * 64 + k * 4 + 1];
            a2 += v * Ms[l * 64 + k * 4 + 2]; a3 += v * Ms[l * 64 + k * 4 + 3];
        }
        ((float4*)g_ae[l])[pos] = make_float4(a0, a1, a2, a3);
    }
}

// ---------------- GEMM: C[M,128] = A'[M,K] @ B[K,128] (+ bias) ----------------
template <int K, bool FUSEBN, bool ATT>
__global__ __launch_bounds__(256) void gemm_kernel(const float* __restrict__ A,
                                                   const float* __restrict__ B,
                                                   const float* __restrict__ bias,
                                                   float* __restrict__ C,
                                                   float* __restrict__ hres,
                                                   const float* __restrict__ att_src,
                                                   const float* __restrict__ att_dst,
                                                   int l, int M) {
    constexpr int AST = K + 4;
    extern __shared__ float sm[];
    float* Bs = sm;               // K*128
    float* As = sm + K * 128;     // 64*AST
    const int t = threadIdx.x;
    const int row0 = blockIdx.x * 64;

    for (int idx = t; idx < K * 32; idx += 256)
        ((float4*)Bs)[idx] = ((const float4*)B)[idx];

    constexpr int KQ = K / 4;
    for (int idx = t; idx < 64 * KQ; idx += 256) {
        int r = idx / KQ, q = idx - r * KQ;
        int grow = row0 + r;
        float4 o = make_float4(0.f, 0.f, 0.f, 0.f);
        if (grow < M) {
            float4 v = ((const float4*)(A + (size_t)grow * K))[q];
            if (FUSEBN) {
                float4 hv = ((const float4*)(hres + (size_t)grow * K))[q];
                float4 sc = __ldg(((const float4*)g_bnscale) + q);
                float4 sh = __ldg(((const float4*)g_bnshift) + q);
                o.x = fmaxf(fmaf(v.x, sc.x, sh.x), 0.f) + hv.x;
                o.y = fmaxf(fmaf(v.y, sc.y, sh.y), 0.f) + hv.y;
                o.z = fmaxf(fmaf(v.z, sc.z, sh.z), 0.f) + hv.z;
                o.w = fmaxf(fmaf(v.w, sc.w, sh.w), 0.f) + hv.w;
                ((float4*)(hres + (size_t)grow * K))[q] = o;
            } else {
                o = v;
            }
        }
        *(float4*)(As + r * AST + 4 * q) = o;
    }
    __syncthreads();

    const int j = t & 15;   // cols 8j..8j+7
    const int i = t >> 4;   // rows 4i..4i+3
    unsigned long long acc2[4][4] = {};

    const float* aBase = As + (4 * i) * AST;
    const ulonglong2* BsP = (const ulonglong2*)Bs;
#pragma unroll 2
    for (int k4 = 0; k4 < K / 4; k4++) {
        float4 av[4];
#pragma unroll
        for (int r = 0; r < 4; r++)
            av[r] = *(const float4*)(aBase + r * AST + 4 * k4);
#pragma unroll
        for (int kk = 0; kk < 4; kk++) {
            int k = 4 * k4 + kk;
            ulonglong2 b01 = BsP[k * 32 + 2 * j];
            ulonglong2 b23 = BsP[k * 32 + 2 * j + 1];
#pragma unroll
            for (int r = 0; r < 4; r++) {
                unsigned long long ap = pack2(((const float*)&av[r])[kk]);
                FMA2(acc2[r][0], ap, b01.x);
                FMA2(acc2[r][1], ap, b01.y);
                FMA2(acc2[r][2], ap, b23.x);
                FMA2(acc2[r][3], ap, b23.y);
            }
        }
    }

    float4 bb0 = make_float4(0.f, 0.f, 0.f, 0.f), bb1 = bb0;
    if (bias) { bb0 = ((const float4*)bias)[2 * j]; bb1 = ((const float4*)bias)[2 * j + 1]; }

    float4 s0, s1, d0, d1;
    if (ATT) {
        s0 = __ldg(((const float4*)(att_src + l * 128)) + 2 * j);
        s1 = __ldg(((const float4*)(att_src + l * 128)) + 2 * j + 1);
        d0 = __ldg(((const float4*)(att_dst + l * 128)) + 2 * j);
        d1 = __ldg(((const float4*)(att_dst + l * 128)) + 2 * j + 1);
    }
    float ps[4], pd[4];

#pragma unroll
    for (int r = 0; r < 4; r++) {
        int grow = row0 + 4 * i + r;
        float2 p0 = unpack2(acc2[r][0]);
        float2 p1 = unpack2(acc2[r][1]);
        float2 p2 = unpack2(acc2[r][2]);
        float2 p3 = unpack2(acc2[r][3]);
        float4 o0 = make_float4(p0.x + bb0.x, p0.y + bb0.y, p1.x + bb0.z, p1.y + bb0.w);
        float4 o1 = make_float4(p2.x + bb1.x, p2.y + bb1.y, p3.x + bb1.z, p3.y + bb1.w);
        if (grow < M) {
            float4* cp = (float4*)(C + (size_t)grow * 128);
            cp[2 * j]     = o0;
            cp[2 * j + 1] = o1;
        }
        if (ATT) {
            ps[r] = o0.x * s0.x + o0.y * s0.y + o0.z * s0.z + o0.w * s0.w
                  + o1.x * s1.x + o1.y * s1.y + o1.z * s1.z + o1.w * s1.w;
            pd[r] = o0.x * d0.x + o0.y * d0.y + o0.z * d0.z + o0.w * d0.w
                  + o1.x * d1.x + o1.y * d1.y + o1.z * d1.z + o1.w * d1.w;
        }
    }

    if (ATT) {
#pragma unroll
        for (int r = 0; r < 4; r++) {
#pragma unroll
            for (int o = 1; o < 4; o <<= 1) {
                ps[r] += __shfl_xor_sync(0xffffffffu, ps[r], o);
                pd[r] += __shfl_xor_sync(0xffffffffu, pd[r], o);
            }
        }
        if ((j & 3) == 0) {
            const int hh = j >> 2;
#pragma unroll
            for (int r = 0; r < 4; r++) {
                int grow = row0 + 4 * i + r;
                if (grow >= M) continue;
                g_asrc[grow * 4 + hh] = ps[r];
                g_adst[grow * 4 + hh] = pd[r];
            }
        }
    }
}

// ---------------- fused GAT: softmax + aggregate + BN stats (fused bnstats tail) ----------------
__global__ __launch_bounds__(256) void gat_kernel(const float* __restrict__ bias_conv,
                                                  const float* __restrict__ gamma,
                                                  const float* __restrict__ beta,
                                                  int l, int N) {
    __shared__ float4 swq[8][64];    // per-warp exp'd weights
    __shared__ int    sid[8][64];    // per-warp neighbor indices
    __shared__ float  sred[8][128];

    const int lane = threadIdx.x & 31;
    const int wl = threadIdx.x >> 5;
    const int warpsTotal = (gridDim.x * blockDim.x) >> 5;
    const int h = lane >> 3;
    const float4* aeB = (const float4*)g_ae[l];
    const float4 bq = __ldg(((const float4*)(bias_conv + l * 128)) + lane);
    const float NEG = -3.0e38f;

    float bs1[4] = {0.f, 0.f, 0.f, 0.f};
    float bs2[4] = {0.f, 0.f, 0.f, 0.f};

    int d = (blockIdx.x * blockDim.x + threadIdx.x) >> 5;
    int start = 0, deg = 0;
    float4 ad, asd;
    if (d < N) {
        start = __ldg(g_rowptr + d);
        deg   = __ldg(g_degi + d);
        ad    = __ldg(((const float4*)g_adst) + d);
        asd   = __ldg(((const float4*)g_asrc) + d);
    }

    while (d < N) {
        // ---- prefetch next node's metadata (hide scalar-load latency) ----
        const int dn = d + warpsTotal;
        int nstart = 0, ndeg = 0;
        float4 nad, nasd;
        if (dn < N) {
            nstart = __ldg(g_rowptr + dn);
            ndeg   = __ldg(g_degi + dn);
            nad    = __ldg(((const float4*)g_adst) + dn);
            nasd   = __ldg(((const float4*)g_asrc) + dn);
        }

        float4 aes = make_float4(0.f, 0.f, 0.f, 0.f);
        float4 den = make_float4(0.f, 0.f, 0.f, 0.f);

        if (deg <= 64) {
            // ---- fast path: no max subtraction (|logit| << 80, exp safe);
            //      single combined warp reduce of aes+den (8 vals, 5 rounds) ----
            const bool v0 = lane < deg, v1 = lane + 32 < deg;
            if (v0) {
                int s = __ldg(g_csrc + start + lane);
                sid[wl][lane] = s;
                float4 as = __ldg(((const float4*)g_asrc) + s);
                float4 ae = __ldg(aeB + start + lane);
                aes.x += ae.x; aes.y += ae.y; aes.z += ae.z; aes.w += ae.w;
                float4 e;
                e.x = __expf(lrelu(as.x + ad.x + ae.x));
                e.y = __expf(lrelu(as.y + ad.y + ae.y));
                e.z = __expf(lrelu(as.z + ad.z + ae.z));
                e.w = __expf(lrelu(as.w + ad.w + ae.w));
                swq[wl][lane] = e;
                den.x += e.x; den.y += e.y; den.z += e.z; den.w += e.w;
            }
            if (v1) {
                int s = __ldg(g_csrc + start + lane + 32);
                sid[wl][lane + 32] = s;
                float4 as = __ldg(((const float4*)g_asrc) + s);
                float4 ae = __ldg(aeB + start + lane + 32);
                aes.x += ae.x; aes.y += ae.y; aes.z += ae.z; aes.w += ae.w;
                float4 e;
                e.x = __expf(lrelu(as.x + ad.x + ae.x));
                e.y = __expf(lrelu(as.y + ad.y + ae.y));
                e.z = __expf(lrelu(as.z + ad.z + ae.z));
                e.w = __expf(lrelu(as.w + ad.w + ae.w));
                swq[wl][lane + 32] = e;
                den.x += e.x; den.y += e.y; den.z += e.z; den.w += e.w;
            }
#pragma unroll
            for (int o = 16; o; o >>= 1) {
                aes.x += __shfl_xor_sync(0xffffffffu, aes.x, o);
                aes.y += __shfl_xor_sync(0xffffffffu, aes.y, o);
                aes.z += __shfl_xor_sync(0xffffffffu, aes.z, o);
                aes.w += __shfl_xor_sync(0xffffffffu, aes.w, o);
                den.x += __shfl_xor_sync(0xffffffffu, den.x, o);
                den.y += __shfl_xor_sync(0xffffffffu, den.y, o);
                den.z += __shfl_xor_sync(0xffffffffu, den.z, o);
                den.w += __shfl_xor_sync(0xffffffffu, den.w, o);
            }
            // self-loop logit: mean of folded edge logits
            float asfh;
            if (deg > 0) {
                float rdeg = 1.f / (float)deg;
                asfh = lrelu(sel4(asd, h) + sel4(ad, h) + sel4(aes, h) * rdeg);
            } else {
                asfh = lrelu(sel4(asd, h) + sel4(ad, h));
            }
            float wsh = __expf(asfh);
            float rdh = 1.f / (sel4(den, h) + wsh + 1e-16f);
            __syncwarp();

            // ---- aggregate: lane = channel quad, unroll 8 for MLP ----
            float4 acc = __ldg(((const float4*)g_xh) + (size_t)d * 32 + lane);
            acc.x *= wsh; acc.y *= wsh; acc.z *= wsh; acc.w *= wsh;
            float4 accB = make_float4(0.f, 0.f, 0.f, 0.f);

            int jj = 0;
            for (; jj + 8 <= deg; jj += 8) {
                int   si[8];
                float wv[8];
#pragma unroll
                for (int q = 0; q < 8; q++) {
                    si[q] = sid[wl][jj + q];
                    wv[q] = sel4(swq[wl][jj + q], h);
                }
                float4 v[8];
#pragma unroll
                for (int q = 0; q < 8; q++)
                    v[q] = __ldg(((const float4*)g_xh) + (size_t)si[q] * 32 + lane);
#pragma unroll
                for (int q = 0; q < 8; q++) {
                    if (q & 1) {
                        accB.x += wv[q] * v[q].x; accB.y += wv[q] * v[q].y;
                        accB.z += wv[q] * v[q].z; accB.w += wv[q] * v[q].w;
                    } else {
                        acc.x += wv[q] * v[q].x; acc.y += wv[q] * v[q].y;
                        acc.z += wv[q] * v[q].z; acc.w += wv[q] * v[q].w;
                    }
                }
            }
            for (; jj + 2 <= deg; jj += 2) {
                int s0i = sid[wl][jj], s1i = sid[wl][jj + 1];
                float w0 = sel4(swq[wl][jj], h), w1 = sel4(swq[wl][jj + 1], h);
                float4 v0q = __ldg(((const float4*)g_xh) + (size_t)s0i * 32 + lane);
                float4 v1q = __ldg(((const float4*)g_xh) + (size_t)s1i * 32 + lane);
                acc.x += w0 * v0q.x; acc.y += w0 * v0q.y;
                acc.z += w0 * v0q.z; acc.w += w0 * v0q.w;
                accB.x += w1 * v1q.x; accB.y += w1 * v1q.y;
                accB.z += w1 * v1q.z; accB.w += w1 * v1q.w;
            }
            if (jj < deg) {
                int s0i = sid[wl][jj];
                float w0 = sel4(swq[wl][jj], h);
                float4 v0q = __ldg(((const float4*)g_xh) + (size_t)s0i * 32 + lane);
                acc.x += w0 * v0q.x; acc.y += w0 * v0q.y;
                acc.z += w0 * v0q.z; acc.w += w0 * v0q.w;
            }
            acc.x += accB.x; acc.y += accB.y; acc.z += accB.z; acc.w += accB.w;

            float4 g;
            g.x = acc.x * rdh + bq.x; g.y = acc.y * rdh + bq.y;
            g.z = acc.z * rdh + bq.z; g.w = acc.w * rdh + bq.w;
            ((float4*)g_acc)[(size_t)d * 32 + lane] = g;
            bs1[0] += g.x; bs1[1] += g.y; bs1[2] += g.z; bs1[3] += g.w;
            bs2[0] += g.x * g.x; bs2[1] += g.y * g.y;
            bs2[2] += g.z * g.z; bs2[3] += g.w * g.w;
        } else {
            // ---- fallback (deg > 64): weights staged in global g_w, with max ----
            float4 m = make_float4(NEG, NEG, NEG, NEG);
            for (int jj = lane; jj < deg; jj += 32) {
                int s = __ldg(g_csrc + start + jj);
                float4 as = __ldg(((const float4*)g_asrc) + s);
                float4 ae = __ldg(aeB + start + jj);
                aes.x += ae.x; aes.y += ae.y; aes.z += ae.z; aes.w += ae.w;
                float4 a;
                a.x = lrelu(as.x + ad.x + ae.x); a.y = lrelu(as.y + ad.y + ae.y);
                a.z = lrelu(as.z + ad.z + ae.z); a.w = lrelu(as.w + ad.w + ae.w);
                ((float4*)g_w)[start + jj] = a;
                m = fmax4(m, a);
            }
#pragma unroll
            for (int o = 16; o; o >>= 1) {
                m.x = fmaxf(m.x, __shfl_xor_sync(0xffffffffu, m.x, o));
                m.y = fmaxf(m.y, __shfl_xor_sync(0xffffffffu, m.y, o));
                m.z = fmaxf(m.z, __shfl_xor_sync(0xffffffffu, m.z, o));
                m.w = fmaxf(m.w, __shfl_xor_sync(0xffffffffu, m.w, o));
                aes.x += __shfl_xor_sync(0xffffffffu, aes.x, o);
                aes.y += __shfl_xor_sync(0xffffffffu, aes.y, o);
                aes.z += __shfl_xor_sync(0xffffffffu, aes.z, o);
                aes.w += __shfl_xor_sync(0xffffffffu, aes.w, o);
            }
            float rdeg = 1.f / (float)deg;
            float4 asf;
            asf.x = lrelu(asd.x + ad.x + aes.x * rdeg);
            asf.y = lrelu(asd.y + ad.y + aes.y * rdeg);
            asf.z = lrelu(asd.z + ad.z + aes.z * rdeg);
            asf.w = lrelu(asd.w + ad.w + aes.w * rdeg);
            m = fmax4(m, asf);

            for (int jj = lane; jj < deg; jj += 32) {
                float4 a = ((const float4*)g_w)[start + jj];
                a.x = __expf(a.x - m.x); a.y = __expf(a.y - m.y);
                a.z = __expf(a.z - m.z); a.w = __expf(a.w - m.w);
                ((float4*)g_w)[start + jj] = a;
                den.x += a.x; den.y += a.y; den.z += a.z; den.w += a.w;
            }
#pragma unroll
            for (int o = 16; o; o >>= 1) {
                den.x += __shfl_xor_sync(0xffffffffu, den.x, o);
                den.y += __shfl_xor_sync(0xffffffffu, den.y, o);
                den.z += __shfl_xor_sync(0xffffffffu, den.z, o);
                den.w += __shfl_xor_sync(0xffffffffu, den.w, o);
            }
            __syncwarp();
            float asfh = sel4(asf, h), mh = sel4(m, h), denh = sel4(den, h);
            float wsh = __expf(asfh - mh);
            float rdh = 1.f / (denh + wsh + 1e-16f);

            float4 acc = __ldg(((const float4*)g_xh) + (size_t)d * 32 + lane);
            acc.x *= wsh; acc.y *= wsh; acc.z *= wsh; acc.w *= wsh;
            for (int jj = 0; jj < deg; jj++) {
                float w = __ldg(g_w + (size_t)(start + jj) * 4 + h);
                int s = __ldg(g_csrc + start + jj);
                float4 v = __ldg(((const float4*)g_xh) + (size_t)s * 32 + lane);
                acc.x += w * v.x; acc.y += w * v.y;
                acc.z += w * v.z; acc.w += w * v.w;
            }
            float4 g;
            g.x = acc.x * rdh + bq.x; g.y = acc.y * rdh + bq.y;
            g.z = acc.z * rdh + bq.z; g.w = acc.w * rdh + bq.w;
            ((float4*)g_acc)[(size_t)d * 32 + lane] = g;
            bs1[0] += g.x; bs1[1] += g.y; bs1[2] += g.z; bs1[3] += g.w;
            bs2[0] += g.x * g.x; bs2[1] += g.y * g.y;
            bs2[2] += g.z * g.z; bs2[3] += g.w * g.w;
        }

        d = dn; start = nstart; deg = ndeg; ad = nad; asd = nasd;
    }

    // block-level BN reduction (8 warps x 128 channels)
#pragma unroll
    for (int q = 0; q < 4; q++) sred[wl][4 * lane + q] = bs1[q];
    __syncthreads();
    if (threadIdx.x < 128) {
        float s = 0.f;
#pragma unroll
        for (int w = 0; w < 8; w++) s += sred[w][threadIdx.x];
        atomicAdd(&g_bnsum[threadIdx.x], (double)s);
    }
    __syncthreads();
#pragma unroll
    for (int q = 0; q < 4; q++) sred[wl][4 * lane + q] = bs2[q];
    __syncthreads();
    if (threadIdx.x < 128) {
        float s = 0.f;
#pragma unroll
        for (int w = 0; w < 8; w++) s += sred[w][threadIdx.x];
        atomicAdd(&g_bnsq[threadIdx.x], (double)s);
    }

    // ---- fused bnstats: last block computes scale/shift, resets sums/counter ----
    __shared__ bool isLast;
    __threadfence();
    if (threadIdx.x == 0)
        isLast = (atomicAdd(&g_ctr, 1u) == gridDim.x - 1u);
    __syncthreads();
    if (isLast) {
        if (threadIdx.x < 128) {
            int c = threadIdx.x;
            double mu = g_bnsum[c] / (double)N;
            double var = g_bnsq[c] / (double)N - mu * mu;
            float rstd = (float)rsqrt(var + 1e-5);
            float ga = gamma[l * 128 + c];
            g_bnscale[c] = ga * rstd;
            g_bnshift[c] = beta[l * 128 + c] - ga * (float)mu * rstd;
            g_bnsum[c] = 0.0;
            g_bnsq[c] = 0.0;
        }
        if (threadIdx.x == 0) g_ctr = 0;
    }
}

// ---------------- launcher ----------------
extern "C" void kernel_launch(void* const* d_in, const int* in_sizes, int n_in,
                              void* d_out, int out_size) {
    (void)n_in; (void)out_size;
    const float* x         = (const float*)d_in[0];
    const int*   ei        = (const int*)  d_in[1];
    const float* edge_attr = (const float*)d_in[2];
    const float* W_atom    = (const float*)d_in[3];
    const float* b_atom    = (const float*)d_in[4];
    const float* W_bond    = (const float*)d_in[5];
    const float* b_bond    = (const float*)d_in[6];
    const float* W_lin     = (const float*)d_in[7];
    const float* W_edge    = (const float*)d_in[8];
    const float* att_src   = (const float*)d_in[9];
    const float* att_dst   = (const float*)d_in[10];
    const float* att_edge  = (const float*)d_in[11];
    const float* bias_conv = (const float*)d_in[12];
    const float* bn_gamma  = (const float*)d_in[13];
    const float* bn_beta   = (const float*)d_in[14];
    const float* W_out     = (const float*)d_in[15];
    const float* b_out     = (const float*)d_in[16];
    float* out = (float*)d_out;

    const int N = in_sizes[0] / 64;
    const int E = in_sizes[1] / 2;
    const int nb = (N + SCAN_BLK - 1) / SCAN_BLK;

    const int smem128 = (128 * 128 + 64 * 132) * 4;
    const int smem64  = (64 * 128 + 64 * 68) * 4;
    cudaFuncSetAttribute(gemm_kernel<128, false, true>,  cudaFuncAttributeMaxDynamicSharedMemorySize, smem128);
    cudaFuncSetAttribute(gemm_kernel<128, true,  true>,  cudaFuncAttributeMaxDynamicSharedMemorySize, smem128);
    cudaFuncSetAttribute(gemm_kernel<128, true,  false>, cudaFuncAttributeMaxDynamicSharedMemorySize, smem128);
    cudaFuncSetAttribute(gemm_kernel<64,  false, false>, cudaFuncAttributeMaxDynamicSharedMemorySize, smem64);

    float* ph;   cudaGetSymbolAddress((void**)&ph,   g_h);
    float* pxh;  cudaGetSymbolAddress((void**)&pxh,  g_xh);
    float* pacc; cudaGetSymbolAddress((void**)&pacc, g_acc);

    // ---- preprocessing: deg, folded consts, CSR counting sort ----
    prep_zero_kernel<<<(N + 255) / 256, 256>>>(N);
    consts_kernel<<<3, 128>>>(W_edge, att_edge, W_bond, b_bond);
    edge_prep_kernel<<<(E + 255) / 256, 256>>>(ei, E);
    scan_sum_kernel<<<nb, SCAN_BLK>>>(N);
    scan_mid_kernel<<<1, 128>>>(nb);
    scan_final_kernel<<<nb, SCAN_BLK>>>(N);
    scatter_kernel<<<(E + 255) / 256, 256>>>(ei, edge_attr, E);

    // ---- atom embedding ----
    gemm_kernel<64, false, false><<<(N + 63) / 64, 256, smem64>>>(
        x, W_atom, b_atom, ph, nullptr, nullptr, nullptr, 0, N);

    for (int l = 0; l < 3; l++) {
        if (l == 0)
            gemm_kernel<128, false, true><<<(N + 63) / 64, 256, smem128>>>(
                ph, W_lin, nullptr, pxh, nullptr, att_src, att_dst, 0, N);
        else
            gemm_kernel<128, true, true><<<(N + 63) / 64, 256, smem128>>>(
                pacc, W_lin + l * 128 * 128, nullptr, pxh, ph, att_src, att_dst, l, N);
        gat_kernel<<<1184, 256>>>(bias_conv, bn_gamma, bn_beta, l, N);
    }

    // output projection with fused BN+ReLU+residual of layer 3
    gemm_kernel<128, true, false><<<(N + 63) / 64, 256, smem128>>>(
        pacc, W_out, b_out, out, ph, nullptr, nullptr, 0, N);
}